// round 13
// baseline (speedup 1.0000x reference)
#include <cuda_runtime.h>
#include <cuda_bf16.h>
#include <math.h>

// Shapes
#define BB   64
#define NN   128
#define EE   256
#define DD   256
#define HH   8
#define MT   384   // N + E
#define NT   129   // N + 1

// ---------------- scratch (device globals; no allocation) ----------------
__device__ float g_qkv [BB*NN*3*DD];
__device__ float g_kve [BB*EE*2*DD];
__device__ float g_attn[BB*NN*DD];
__device__ float g_rkv [BB*NT*2*DD];

// bf16 hi/lo weight buffers, layout [Nc][256] (k contiguous)
#define OFF_QKV   0
#define OFF_KVE   (OFF_QKV + 768*256)
#define OFF_W1    (OFF_KVE + 512*256)
#define OFF_W2    (OFF_W1  + 256*256)
#define OFF_ROKV  (OFF_W2  + 256*256)
#define W_CONV    (OFF_ROKV+ 512*256)
__device__ __nv_bfloat16 g_whi[W_CONV];
__device__ __nv_bfloat16 g_wlo[W_CONV];

// ---------------- fused weight conversion (one launch) -------------------
__global__ void conv_all(const float* __restrict__ w_qkv,
                         const float* __restrict__ w_kve,
                         const float* __restrict__ w1,
                         const float* __restrict__ w2,
                         const float* __restrict__ ro_w_kv,
                         __nv_bfloat16* __restrict__ hi,
                         __nv_bfloat16* __restrict__ lo) {
    int i = blockIdx.x * 256 + threadIdx.x;
    if (i >= W_CONV) return;
    const float* W; int Nc; bool direct; int off;
    if      (i < OFF_KVE ) { W = w_qkv;   Nc = 768; direct = false; off = OFF_QKV;  }
    else if (i < OFF_W1  ) { W = w_kve;   Nc = 512; direct = false; off = OFF_KVE;  }
    else if (i < OFF_W2  ) { W = w1;      Nc = 256; direct = true;  off = OFF_W1;   }
    else if (i < OFF_ROKV) { W = w2;      Nc = 256; direct = true;  off = OFF_W2;   }
    else                   { W = ro_w_kv; Nc = 512; direct = false; off = OFF_ROKV; }
    int li = i - off;
    int n = li >> 8, k = li & 255;
    float v = direct ? W[(size_t)n * 256 + k] : W[(size_t)k * Nc + n];
    __nv_bfloat16 h = __float2bfloat16(v);
    hi[i] = h;
    lo[i] = __float2bfloat16(v - __bfloat162float(h));
}

// ---------------- mma / ldmatrix / cp.async helpers -----------------------
__device__ __forceinline__ void mma_bf16(float* c, const unsigned* a, const unsigned* b) {
    asm volatile(
        "mma.sync.aligned.m16n8k16.row.col.f32.bf16.bf16.f32 "
        "{%0,%1,%2,%3}, {%4,%5,%6,%7}, {%8,%9}, {%0,%1,%2,%3};\n"
        : "+f"(c[0]), "+f"(c[1]), "+f"(c[2]), "+f"(c[3])
        : "r"(a[0]), "r"(a[1]), "r"(a[2]), "r"(a[3]), "r"(b[0]), "r"(b[1]));
}

__device__ __forceinline__ void ldsm4(unsigned* r, const void* p) {
    unsigned a = (unsigned)__cvta_generic_to_shared(p);
    asm volatile("ldmatrix.sync.aligned.m8n8.x4.shared.b16 {%0,%1,%2,%3}, [%4];"
                 : "=r"(r[0]), "=r"(r[1]), "=r"(r[2]), "=r"(r[3]) : "r"(a));
}

__device__ __forceinline__ void cpa16(void* s, const void* g) {
    unsigned a = (unsigned)__cvta_generic_to_shared(s);
    asm volatile("cp.async.cg.shared.global [%0], [%1], 16;" :: "r"(a), "l"(g));
}
#define CP_COMMIT() asm volatile("cp.async.commit_group;" ::: "memory")
#define CP_WAIT0()  asm volatile("cp.async.wait_group 0;" ::: "memory")

// packed-cvt hi/lo split: low half = x, high half = y
__device__ __forceinline__ void split2(float x, float y, unsigned& hi, unsigned& lo) {
    unsigned h;
    asm("cvt.rn.bf16x2.f32 %0, %1, %2;" : "=r"(h) : "f"(y), "f"(x));
    float fx = __uint_as_float(h << 16);
    float fy = __uint_as_float(h & 0xffff0000u);
    unsigned l;
    asm("cvt.rn.bf16x2.f32 %0, %1, %2;" : "=r"(l) : "f"(y - fy), "f"(x - fx));
    hi = h; lo = l;
}

#define GST 72   // smem row stride in bf16 (144B)
#define GEMM_SMEM ((2*64*GST + 4*128*GST) * (int)sizeof(__nv_bfloat16))   // 92160

// ---------------- bf16-split tensor-core GEMM (BM=64, pipelined) ----------
template<bool RELU, bool CONCAT, bool DUAL>
__global__ void __launch_bounds__(256)
gemm_mma(const float* __restrict__ A, const float* __restrict__ A2,
         const __nv_bfloat16* __restrict__ Whi,
         const __nv_bfloat16* __restrict__ Wlo,
         const float* __restrict__ bias,
         float* __restrict__ C, int M, int Nc,
         const __nv_bfloat16* Whi2, const __nv_bfloat16* Wlo2,
         const float* bias2, float* C2, int M2, int Nc2,
         int nb0, int gx0, int gx1) {
    extern __shared__ __nv_bfloat16 sm[];
    __nv_bfloat16* sAhi = sm;
    __nv_bfloat16* sAlo = sAhi + 64 * GST;
    __nv_bfloat16* sBhi = sAlo + 64 * GST;
    __nv_bfloat16* sBlo = sBhi + 2 * 128 * GST;

    int bx, by;
    const float* Ap = A;
    const __nv_bfloat16* Whip = Whi;
    const __nv_bfloat16* Wlop = Wlo;
    const float* biasp = bias;
    float* Cp = C;
    int Mp = M, Ncp = Nc;
    if (DUAL) {
        int bid = blockIdx.x;
        if (bid < nb0) { bx = bid % gx0; by = bid / gx0; }
        else {
            bid -= nb0; bx = bid % gx1; by = bid / gx1;
            Ap = A2; Whip = Whi2; Wlop = Wlo2; biasp = bias2; Cp = C2;
            Mp = M2; Ncp = Nc2;
        }
    } else {
        bx = blockIdx.x; by = blockIdx.y;
    }

    int tid = threadIdx.x;
    int lane = tid & 31, warp = tid >> 5;
    int g = lane >> 2, tq = lane & 3;
    int mbase = (warp >> 2) * 32;
    int nbase = (warp & 3) * 32;
    int m0 = by * 64;
    int n0 = bx * 128;

    int lr = lane & 7, sel = lane >> 3;
    const __nv_bfloat16* aHiB = sAhi + (size_t)(mbase + (sel & 1) * 8 + lr) * GST + ((sel >> 1) & 1) * 8;
    const __nv_bfloat16* aLoB = sAlo + (size_t)(mbase + (sel & 1) * 8 + lr) * GST + ((sel >> 1) & 1) * 8;
    size_t bOff = (size_t)(nbase + (sel >> 1) * 8 + lr) * GST + (sel & 1) * 8;

    int ar = tid >> 2, aq = tid & 3;
    int arr = m0 + ar;
    bool avalid = arr < Mp;
    const float* aRow;
    if (CONCAT) {
        int bidx = arr / NT, t = arr - bidx * NT;
        aRow = (t == 0) ? A2 + (size_t)bidx * 256
                        : Ap + (size_t)(bidx * NN + t - 1) * 256;
    } else {
        aRow = Ap + (size_t)arr * 256;
    }
    int colb = aq * 16;
    aRow += colb;

    int bn = tid >> 1, bck = (tid & 1) * 32;

    float acc[2][4][4];
#pragma unroll
    for (int mt = 0; mt < 2; mt++)
#pragma unroll
        for (int nt = 0; nt < 4; nt++)
#pragma unroll
            for (int i = 0; i < 4; i++) acc[mt][nt][i] = 0.f;

    float4 av[4];
    {
        const __nv_bfloat16* wh = Whip + (size_t)(n0 + bn) * 256 + bck;
        const __nv_bfloat16* wl = Wlop + (size_t)(n0 + bn) * 256 + bck;
        __nv_bfloat16* dh = sBhi + (size_t)bn * GST + bck;
        __nv_bfloat16* dl = sBlo + (size_t)bn * GST + bck;
#pragma unroll
        for (int i = 0; i < 4; i++) {
            cpa16(dh + i * 8, wh + i * 8);
            cpa16(dl + i * 8, wl + i * 8);
        }
        CP_COMMIT();
#pragma unroll
        for (int i = 0; i < 4; i++)
            av[i] = avalid ? *(const float4*)(aRow + i * 4)
                           : make_float4(0.f, 0.f, 0.f, 0.f);
#pragma unroll
        for (int i = 0; i < 4; i++) {
            unsigned h01, l01, h23, l23;
            split2(av[i].x, av[i].y, h01, l01);
            split2(av[i].z, av[i].w, h23, l23);
            int c = colb + i * 4;
            *(unsigned*)(sAhi + (size_t)ar * GST + c)     = h01;
            *(unsigned*)(sAhi + (size_t)ar * GST + c + 2) = h23;
            *(unsigned*)(sAlo + (size_t)ar * GST + c)     = l01;
            *(unsigned*)(sAlo + (size_t)ar * GST + c + 2) = l23;
        }
        CP_WAIT0();
        __syncthreads();
    }

    for (int it = 0; it < 4; it++) {
        int nk = it + 1;
        if (nk < 4) {
            int buf = nk & 1;
            const __nv_bfloat16* wh = Whip + (size_t)(n0 + bn) * 256 + nk * 64 + bck;
            const __nv_bfloat16* wl = Wlop + (size_t)(n0 + bn) * 256 + nk * 64 + bck;
            __nv_bfloat16* dh = sBhi + (size_t)buf * 128 * GST + (size_t)bn * GST + bck;
            __nv_bfloat16* dl = sBlo + (size_t)buf * 128 * GST + (size_t)bn * GST + bck;
#pragma unroll
            for (int i = 0; i < 4; i++) {
                cpa16(dh + i * 8, wh + i * 8);
                cpa16(dl + i * 8, wl + i * 8);
            }
            CP_COMMIT();
#pragma unroll
            for (int i = 0; i < 4; i++)
                av[i] = avalid ? *(const float4*)(aRow + nk * 64 + i * 4)
                               : make_float4(0.f, 0.f, 0.f, 0.f);
        }

        {
            size_t bufo = (size_t)(it & 1) * 128 * GST;
            const __nv_bfloat16* bHiB = sBhi + bufo + bOff;
            const __nv_bfloat16* bLoB = sBlo + bufo + bOff;
#pragma unroll
            for (int kk = 0; kk < 64; kk += 16) {
                unsigned ah[2][4], al[2][4], bh[4][2], bl[4][2];
#pragma unroll
                for (int mt = 0; mt < 2; mt++) {
                    ldsm4(ah[mt], aHiB + (size_t)mt * 16 * GST + kk);
                    ldsm4(al[mt], aLoB + (size_t)mt * 16 * GST + kk);
                }
#pragma unroll
                for (int p = 0; p < 2; p++) {
                    unsigned t[4];
                    ldsm4(t, bHiB + (size_t)p * 16 * GST + kk);
                    bh[2*p][0] = t[0]; bh[2*p][1] = t[1];
                    bh[2*p+1][0] = t[2]; bh[2*p+1][1] = t[3];
                    ldsm4(t, bLoB + (size_t)p * 16 * GST + kk);
                    bl[2*p][0] = t[0]; bl[2*p][1] = t[1];
                    bl[2*p+1][0] = t[2]; bl[2*p+1][1] = t[3];
                }
#pragma unroll
                for (int mt = 0; mt < 2; mt++)
#pragma unroll
                    for (int nt = 0; nt < 4; nt++) {
                        mma_bf16(acc[mt][nt], ah[mt], bh[nt]);
                        mma_bf16(acc[mt][nt], al[mt], bh[nt]);
                        mma_bf16(acc[mt][nt], ah[mt], bl[nt]);
                    }
            }
        }
        __syncthreads();
        if (nk < 4) {
#pragma unroll
            for (int i = 0; i < 4; i++) {
                unsigned h01, l01, h23, l23;
                split2(av[i].x, av[i].y, h01, l01);
                split2(av[i].z, av[i].w, h23, l23);
                int c = colb + i * 4;
                *(unsigned*)(sAhi + (size_t)ar * GST + c)     = h01;
                *(unsigned*)(sAhi + (size_t)ar * GST + c + 2) = h23;
                *(unsigned*)(sAlo + (size_t)ar * GST + c)     = l01;
                *(unsigned*)(sAlo + (size_t)ar * GST + c + 2) = l23;
            }
            CP_WAIT0();
            __syncthreads();
        }
    }

#pragma unroll
    for (int mt = 0; mt < 2; mt++) {
        int r0 = m0 + mbase + mt * 16 + g;
#pragma unroll
        for (int nt = 0; nt < 4; nt++) {
            int col = n0 + nbase + nt * 8 + tq * 2;
            float b0 = biasp[col], b1 = biasp[col + 1];
            if (r0 < Mp) {
                float v0 = acc[mt][nt][0] + b0;
                float v1 = acc[mt][nt][1] + b1;
                if (RELU) { v0 = fmaxf(v0, 0.f); v1 = fmaxf(v1, 0.f); }
                Cp[(size_t)r0 * Ncp + col]     = v0;
                Cp[(size_t)r0 * Ncp + col + 1] = v1;
            }
            if (r0 + 8 < Mp) {
                float v2 = acc[mt][nt][2] + b0;
                float v3 = acc[mt][nt][3] + b1;
                if (RELU) { v2 = fmaxf(v2, 0.f); v3 = fmaxf(v3, 0.f); }
                Cp[(size_t)(r0 + 8) * Ncp + col]     = v2;
                Cp[(size_t)(r0 + 8) * Ncp + col + 1] = v3;
            }
        }
    }
}

// ---------------- flash attention on tensor cores -------------------------
#define AK_STR 40
#define AV_STR 392
#define ATT2_SMEM ((384*AK_STR + 2*32*AV_STR) * (int)sizeof(__nv_bfloat16))

__global__ void __launch_bounds__(256, 2)
attn_flash(const float* __restrict__ qkv,
           const float* __restrict__ kve,
           const unsigned char* __restrict__ nmask,
           float* __restrict__ out) {
    int h = blockIdx.x, b = blockIdx.y;
    extern __shared__ __nv_bfloat16 smb[];
    __nv_bfloat16* Khi  = smb;
    __nv_bfloat16* Vthi = Khi  + 384 * AK_STR;
    __nv_bfloat16* Vtlo = Vthi + 32 * AV_STR;

    int tid = threadIdx.x;
    for (int idx = tid; idx < MT * 32; idx += 256) {
        int m = idx >> 5, d = idx & 31;
        float kv, vv;
        if (m < NN) {
            const float* base = qkv + (size_t)(b * NN + m) * 768 + h * 32 + d;
            kv = base[256]; vv = base[512];
        } else {
            const float* base = kve + (size_t)(b * EE + (m - NN)) * 512 + h * 32 + d;
            kv = base[0];   vv = base[256];
        }
        Khi[m * AK_STR + d] = __float2bfloat16(kv);
        __nv_bfloat16 vh = __float2bfloat16(vv);
        Vthi[d * AV_STR + m] = vh;
        Vtlo[d * AV_STR + m] = __float2bfloat16(vv - __bfloat162float(vh));
    }
    __syncthreads();

    int lane = tid & 31, warp = tid >> 5;
    int g = lane >> 2, tq = lane & 3;
    int lr = lane & 7, sel = lane >> 3;
    int r0 = warp * 16 + g;
    int r1 = r0 + 8;
    const float scale = 0.17677669529663687f;

    const __nv_bfloat16* kHiB = Khi  + (size_t)((sel >> 1) * 8 + lr) * AK_STR + (sel & 1) * 8;
    const __nv_bfloat16* vHiB = Vthi + (size_t)((sel >> 1) * 8 + lr) * AV_STR + (sel & 1) * 8;
    const __nv_bfloat16* vLoB = Vtlo + (size_t)((sel >> 1) * 8 + lr) * AV_STR + (sel & 1) * 8;

    unsigned qh[2][4], ql[2][4];
    {
        const float* q0p = qkv + (size_t)(b * NN + r0) * 768 + h * 32;
        const float* q1p = qkv + (size_t)(b * NN + r1) * 768 + h * 32;
#pragma unroll
        for (int kk2 = 0; kk2 < 2; kk2++) {
            int kb = kk2 * 16 + tq * 2;
            float2 v;
            v = *(const float2*)(q0p + kb);
            split2(v.x * scale, v.y * scale, qh[kk2][0], ql[kk2][0]);
            v = *(const float2*)(q1p + kb);
            split2(v.x * scale, v.y * scale, qh[kk2][1], ql[kk2][1]);
            v = *(const float2*)(q0p + kb + 8);
            split2(v.x * scale, v.y * scale, qh[kk2][2], ql[kk2][2]);
            v = *(const float2*)(q1p + kb + 8);
            split2(v.x * scale, v.y * scale, qh[kk2][3], ql[kk2][3]);
        }
    }

    const unsigned short* mrow0 =
        (const unsigned short*)(nmask + (size_t)(b * NN + r0) * MT);
    const unsigned short* mrow1 =
        (const unsigned short*)(nmask + (size_t)(b * NN + r1) * MT);

    float m0 = -INFINITY, m1 = -INFINITY, l0 = 0.f, l1 = 0.f;
    float o[4][4];
#pragma unroll
    for (int nt = 0; nt < 4; nt++)
#pragma unroll
        for (int i = 0; i < 4; i++) o[nt][i] = 0.f;

#pragma unroll
    for (int c = 0; c < 6; c++) {
        int tkb = c * 64;
        float s[8][4];
#pragma unroll
        for (int nt = 0; nt < 8; nt++)
#pragma unroll
            for (int i = 0; i < 4; i++) s[nt][i] = 0.f;

#pragma unroll
        for (int kk2 = 0; kk2 < 2; kk2++) {
#pragma unroll
            for (int p = 0; p < 4; p++) {
                unsigned t[4];
                ldsm4(t, kHiB + (size_t)(tkb + p * 16) * AK_STR + kk2 * 16);
                unsigned bhA[2] = { t[0], t[1] }, bhB[2] = { t[2], t[3] };
                mma_bf16(s[2*p],   qh[kk2], bhA);
                mma_bf16(s[2*p],   ql[kk2], bhA);
                mma_bf16(s[2*p+1], qh[kk2], bhB);
                mma_bf16(s[2*p+1], ql[kk2], bhB);
            }
        }

        float cm0 = -INFINITY, cm1 = -INFINITY;
#pragma unroll
        for (int nt = 0; nt < 8; nt++) {
            int t = tkb + nt * 8 + tq * 2;
            unsigned short mm0 = mrow0[t >> 1];
            unsigned short mm1 = mrow1[t >> 1];
            if (mm0 & 0x00FFu) s[nt][0] = -INFINITY;
            if (mm0 & 0xFF00u) s[nt][1] = -INFINITY;
            if (mm1 & 0x00FFu) s[nt][2] = -INFINITY;
            if (mm1 & 0xFF00u) s[nt][3] = -INFINITY;
            cm0 = fmaxf(cm0, fmaxf(s[nt][0], s[nt][1]));
            cm1 = fmaxf(cm1, fmaxf(s[nt][2], s[nt][3]));
        }
        cm0 = fmaxf(cm0, __shfl_xor_sync(0xffffffffu, cm0, 1));
        cm0 = fmaxf(cm0, __shfl_xor_sync(0xffffffffu, cm0, 2));
        cm1 = fmaxf(cm1, __shfl_xor_sync(0xffffffffu, cm1, 1));
        cm1 = fmaxf(cm1, __shfl_xor_sync(0xffffffffu, cm1, 2));

        float nm0 = fmaxf(m0, cm0), nm1 = fmaxf(m1, cm1);
        float corr0 = (m0 == -INFINITY) ? 0.f : __expf(m0 - nm0);
        float corr1 = (m1 == -INFINITY) ? 0.f : __expf(m1 - nm1);
        float e0 = (nm0 == -INFINITY) ? 0.f : nm0;
        float e1 = (nm1 == -INFINITY) ? 0.f : nm1;
        m0 = nm0; m1 = nm1;
        l0 *= corr0; l1 *= corr1;
#pragma unroll
        for (int nt = 0; nt < 4; nt++) {
            o[nt][0] *= corr0; o[nt][1] *= corr0;
            o[nt][2] *= corr1; o[nt][3] *= corr1;
        }

#pragma unroll
        for (int ks = 0; ks < 4; ks++) {
            float p00 = __expf(s[2*ks][0]   - e0);
            float p01 = __expf(s[2*ks][1]   - e0);
            float p02 = __expf(s[2*ks][2]   - e1);
            float p03 = __expf(s[2*ks][3]   - e1);
            float p10 = __expf(s[2*ks+1][0] - e0);
            float p11 = __expf(s[2*ks+1][1] - e0);
            float p12 = __expf(s[2*ks+1][2] - e1);
            float p13 = __expf(s[2*ks+1][3] - e1);
            l0 += p00 + p01 + p10 + p11;
            l1 += p02 + p03 + p12 + p13;
            unsigned ah[4], al[4];
            split2(p00, p01, ah[0], al[0]);
            split2(p02, p03, ah[1], al[1]);
            split2(p10, p11, ah[2], al[2]);
            split2(p12, p13, ah[3], al[3]);
#pragma unroll
            for (int p = 0; p < 2; p++) {
                unsigned t[4], u[4];
                ldsm4(t, vHiB + (size_t)p * 16 * AV_STR + tkb + ks * 16);
                ldsm4(u, vLoB + (size_t)p * 16 * AV_STR + tkb + ks * 16);
                unsigned bhA[2] = { t[0], t[1] }, bhB[2] = { t[2], t[3] };
                unsigned blA[2] = { u[0], u[1] }, blB[2] = { u[2], u[3] };
                mma_bf16(o[2*p],   ah, bhA);
                mma_bf16(o[2*p],   al, bhA);
                mma_bf16(o[2*p],   ah, blA);
                mma_bf16(o[2*p+1], ah, bhB);
                mma_bf16(o[2*p+1], al, bhB);
                mma_bf16(o[2*p+1], ah, blB);
            }
        }
    }

    l0 += __shfl_xor_sync(0xffffffffu, l0, 1);
    l0 += __shfl_xor_sync(0xffffffffu, l0, 2);
    l1 += __shfl_xor_sync(0xffffffffu, l1, 1);
    l1 += __shfl_xor_sync(0xffffffffu, l1, 2);
    float inv0 = 1.f / l0, inv1 = 1.f / l1;
    size_t ob0 = (size_t)(b * NN + r0) * DD + h * 32;
    size_t ob1 = (size_t)(b * NN + r1) * DD + h * 32;
#pragma unroll
    for (int nt = 0; nt < 4; nt++) {
        int dcol = nt * 8 + tq * 2;
        *(float2*)(out + ob0 + dcol) = make_float2(o[nt][0] * inv0, o[nt][1] * inv0);
        *(float2*)(out + ob1 + dcol) = make_float2(o[nt][2] * inv1, o[nt][3] * inv1);
    }
}

// ---------------- fused FFN megakernel (512 threads, 16 warps) ------------
// Block = 64 rows: LN(node_x+attn) -> GEMM1(relu) -> GEMM2 -> +res -> LN
// Warp grid 2(m)x8(n), warp tile 32x32.
#define XST 264   // x1/h1 row stride in bf16
#define WST 40    // W chunk row stride in bf16 (KC=32 + pad)
#define VST 260   // fp32 temp row stride
#define FFN_SMEM ((4*64*XST + 2*2*256*WST) * (int)sizeof(__nv_bfloat16))  // 217088

__global__ void __launch_bounds__(512)
ffn_fused(const float* __restrict__ nx, const float* __restrict__ at,
          const __nv_bfloat16* __restrict__ w1hi, const __nv_bfloat16* __restrict__ w1lo,
          const __nv_bfloat16* __restrict__ w2hi, const __nv_bfloat16* __restrict__ w2lo,
          const float* __restrict__ b1, const float* __restrict__ b2,
          const float* __restrict__ g1, const float* __restrict__ be1,
          const float* __restrict__ g2, const float* __restrict__ be2,
          float* __restrict__ out_x) {
    extern __shared__ __nv_bfloat16 sm[];
    __nv_bfloat16* x1hi = sm;
    __nv_bfloat16* x1lo = x1hi + 64 * XST;
    __nv_bfloat16* h1hi = x1lo + 64 * XST;
    __nv_bfloat16* h1lo = h1hi + 64 * XST;
    __nv_bfloat16* sW   = h1lo + 64 * XST;      // [buf][hi/lo][256][WST]
    float* vtmp = (float*)h1hi;                  // phase-0 temp (64xVST)
    float* utmp = (float*)sW;                    // final temp   (64xVST)

    int tid = threadIdx.x;
    int lane = tid & 31, warp = tid >> 5;
    int g = lane >> 2, tq = lane & 3;
    int lr = lane & 7, sel = lane >> 3;
    int mbase = (warp >> 3) * 32;     // 0 or 32
    int wn = warp & 7;                // n-slice of 32 cols
    int m0 = blockIdx.x * 64;

    // W staging slice: 2 threads per row, 16 cols each (per chunk of 32)
    int wr = tid >> 1, wq = (tid & 1) * 16;

    // ---- issue W1 chunk0 early (hides under phase 0) ----
    {
        const __nv_bfloat16* wh = w1hi + (size_t)wr * 256 + wq;
        const __nv_bfloat16* wl = w1lo + (size_t)wr * 256 + wq;
        __nv_bfloat16* dh = sW + (size_t)wr * WST + wq;
        __nv_bfloat16* dl = sW + 256 * WST + (size_t)wr * WST + wq;
        cpa16(dh, wh);     cpa16(dh + 8, wh + 8);
        cpa16(dl, wl);     cpa16(dl + 8, wl + 8);
        CP_COMMIT();
    }

    // ---- phase 0: x1 = LN(node_x + attn), 8 threads per row ----
    {
        int r = tid >> 3, q = tid & 7;
        const float* nrow = nx + (size_t)(m0 + r) * 256;
        const float* arow = at + (size_t)(m0 + r) * 256;
        float s1 = 0.f;
#pragma unroll
        for (int i = 0; i < 8; i++) {
            int col = q * 32 + i * 4;
            float4 v = *(const float4*)(nrow + col);
            float4 a = *(const float4*)(arow + col);
            v.x += a.x; v.y += a.y; v.z += a.z; v.w += a.w;
            *(float4*)(vtmp + (size_t)r * VST + col) = v;
            s1 += v.x + v.y + v.z + v.w;
        }
        s1 += __shfl_xor_sync(0xffffffffu, s1, 1);
        s1 += __shfl_xor_sync(0xffffffffu, s1, 2);
        s1 += __shfl_xor_sync(0xffffffffu, s1, 4);
        float mean = s1 * (1.f / 256.f);
        float s2 = 0.f;
#pragma unroll
        for (int i = 0; i < 8; i++) {
            int col = q * 32 + i * 4;
            float4 v = *(float4*)(vtmp + (size_t)r * VST + col);
            v.x -= mean; v.y -= mean; v.z -= mean; v.w -= mean;
            *(float4*)(vtmp + (size_t)r * VST + col) = v;
            s2 += v.x * v.x + v.y * v.y + v.z * v.z + v.w * v.w;
        }
        s2 += __shfl_xor_sync(0xffffffffu, s2, 1);
        s2 += __shfl_xor_sync(0xffffffffu, s2, 2);
        s2 += __shfl_xor_sync(0xffffffffu, s2, 4);
        float rstd = rsqrtf(s2 * (1.f / 256.f) + 1e-5f);
#pragma unroll
        for (int i = 0; i < 8; i++) {
            int col = q * 32 + i * 4;
            float4 v = *(float4*)(vtmp + (size_t)r * VST + col);
            float4 gg = *(const float4*)(g1 + col);
            float4 bb = *(const float4*)(be1 + col);
            float x0 = v.x * rstd * gg.x + bb.x;
            float x1 = v.y * rstd * gg.y + bb.y;
            float x2 = v.z * rstd * gg.z + bb.z;
            float x3 = v.w * rstd * gg.w + bb.w;
            unsigned h01, l01, h23, l23;
            split2(x0, x1, h01, l01);
            split2(x2, x3, h23, l23);
            *(unsigned*)(x1hi + (size_t)r * XST + col)     = h01;
            *(unsigned*)(x1hi + (size_t)r * XST + col + 2) = h23;
            *(unsigned*)(x1lo + (size_t)r * XST + col)     = l01;
            *(unsigned*)(x1lo + (size_t)r * XST + col + 2) = l23;
        }
    }
    CP_WAIT0();
    __syncthreads();

    // frag base pointers
    const __nv_bfloat16* a1HiB = x1hi + (size_t)(mbase + (sel & 1) * 8 + lr) * XST + ((sel >> 1) & 1) * 8;
    const __nv_bfloat16* a1LoB = x1lo + (size_t)(mbase + (sel & 1) * 8 + lr) * XST + ((sel >> 1) & 1) * 8;
    const __nv_bfloat16* a2HiB = h1hi + (size_t)(mbase + (sel & 1) * 8 + lr) * XST + ((sel >> 1) & 1) * 8;
    const __nv_bfloat16* a2LoB = h1lo + (size_t)(mbase + (sel & 1) * 8 + lr) * XST + ((sel >> 1) & 1) * 8;
    size_t bOff = (size_t)(wn * 32 + (sel >> 1) * 8 + lr) * WST + (sel & 1) * 8;

    float acc[2][4][4];
#pragma unroll
    for (int mt = 0; mt < 2; mt++)
#pragma unroll
        for (int nt = 0; nt < 4; nt++)
#pragma unroll
            for (int i = 0; i < 4; i++) acc[mt][nt][i] = 0.f;

    // ---- GEMM1: h1 = relu(x1 @ W1^T + b1), KC=32 double-buffered ----
#pragma unroll
    for (int ck = 0; ck < 8; ck++) {
        if (ck < 7) {
            int buf = (ck + 1) & 1;
            const __nv_bfloat16* wh = w1hi + (size_t)wr * 256 + (ck + 1) * 32 + wq;
            const __nv_bfloat16* wl = w1lo + (size_t)wr * 256 + (ck + 1) * 32 + wq;
            __nv_bfloat16* dh = sW + (size_t)buf * 2 * 256 * WST + (size_t)wr * WST + wq;
            __nv_bfloat16* dl = dh + 256 * WST;
            cpa16(dh, wh);     cpa16(dh + 8, wh + 8);
            cpa16(dl, wl);     cpa16(dl + 8, wl + 8);
            CP_COMMIT();
        }
        size_t bufo = (size_t)(ck & 1) * 2 * 256 * WST;
#pragma unroll
        for (int kk = 0; kk < 32; kk += 16) {
            unsigned ah[2][4], al[2][4];
#pragma unroll
            for (int mt = 0; mt < 2; mt++) {
                ldsm4(ah[mt], a1HiB + (size_t)mt * 16 * XST + ck * 32 + kk);
                ldsm4(al[mt], a1LoB + (size_t)mt * 16 * XST + ck * 32 + kk);
            }
#pragma unroll
            for (int p = 0; p < 2; p++) {
                unsigned t[4], u[4];
                ldsm4(t, sW + bufo + bOff + (size_t)p * 16 * WST + kk);
                ldsm4(u, sW + bufo + 256 * WST + bOff + (size_t)p * 16 * WST + kk);
                unsigned bhA[2] = { t[0], t[1] }, bhB[2] = { t[2], t[3] };
                unsigned blA[2] = { u[0], u[1] }, blB[2] = { u[2], u[3] };
#pragma unroll
                for (int mt = 0; mt < 2; mt++) {
                    mma_bf16(acc[mt][2*p],   ah[mt], bhA);
                    mma_bf16(acc[mt][2*p],   al[mt], bhA);
                    mma_bf16(acc[mt][2*p],   ah[mt], blA);
                    mma_bf16(acc[mt][2*p+1], ah[mt], bhB);
                    mma_bf16(acc[mt][2*p+1], al[mt], bhB);
                    mma_bf16(acc[mt][2*p+1], ah[mt], blB);
                }
            }
        }
        if (ck < 7) { CP_WAIT0(); }
        __syncthreads();
    }

    // issue W2 chunk0 (into buf0; last read of buf0 was ck=6)
    {
        const __nv_bfloat16* wh = w2hi + (size_t)wr * 256 + wq;
        const __nv_bfloat16* wl = w2lo + (size_t)wr * 256 + wq;
        __nv_bfloat16* dh = sW + (size_t)wr * WST + wq;
        __nv_bfloat16* dl = sW + 256 * WST + (size_t)wr * WST + wq;
        cpa16(dh, wh);     cpa16(dh + 8, wh + 8);
        cpa16(dl, wl);     cpa16(dl + 8, wl + 8);
        CP_COMMIT();
    }

    // epilogue1: h1 = relu(acc + b1) -> smem hi/lo; reset acc
#pragma unroll
    for (int mt = 0; mt < 2; mt++) {
        int r0 = mbase + mt * 16 + g;
#pragma unroll
        for (int nt = 0; nt < 4; nt++) {
            int col = wn * 32 + nt * 8 + tq * 2;
            float bb0 = b1[col], bb1 = b1[col + 1];
            float v0 = fmaxf(acc[mt][nt][0] + bb0, 0.f);
            float v1 = fmaxf(acc[mt][nt][1] + bb1, 0.f);
            float v2 = fmaxf(acc[mt][nt][2] + bb0, 0.f);
            float v3 = fmaxf(acc[mt][nt][3] + bb1, 0.f);
            unsigned h01, l01, h23, l23;
            split2(v0, v1, h01, l01);
            split2(v2, v3, h23, l23);
            *(unsigned*)(h1hi + (size_t)r0 * XST + col)       = h01;
            *(unsigned*)(h1lo + (size_t)r0 * XST + col)       = l01;
            *(unsigned*)(h1hi + (size_t)(r0 + 8) * XST + col) = h23;
            *(unsigned*)(h1lo + (size_t)(r0 + 8) * XST + col) = l23;
            acc[mt][nt][0] = 0.f; acc[mt][nt][1] = 0.f;
            acc[mt][nt][2] = 0.f; acc[mt][nt][3] = 0.f;
        }
    }
    CP_WAIT0();
    __syncthreads();

    // ---- GEMM2: ff = h1 @ W2^T ----
#pragma unroll
    for (int ck = 0; ck < 8; ck++) {
        if (ck < 7) {
            int buf = (ck + 1) & 1;
            const __nv_bfloat16* wh = w2hi + (size_t)wr * 256 + (ck + 1) * 32 + wq;
            const __nv_bfloat16* wl = w2lo + (size_t)wr * 256 + (ck + 1) * 32 + wq;
            __nv_bfloat16* dh = sW + (size_t)buf * 2 * 256 * WST + (size_t)wr * WST + wq;
            __nv_bfloat16* dl = dh + 256 * WST;
            cpa16(dh, wh);     cpa16(dh + 8, wh + 8);
            cpa16(dl, wl);     cpa16(dl + 8, wl + 8);
            CP_COMMIT();
        }
        size_t bufo = (size_t)(ck & 1) * 2 * 256 * WST;
#pragma unroll
        for (int kk = 0; kk < 32; kk += 16) {
            unsigned ah[2][4], al[2][4];
#pragma unroll
            for (int mt = 0; mt < 2; mt++) {
                ldsm4(ah[mt], a2HiB + (size_t)mt * 16 * XST + ck * 32 + kk);
                ldsm4(al[mt], a2LoB + (size_t)mt * 16 * XST + ck * 32 + kk);
            }
#pragma unroll
            for (int p = 0; p < 2; p++) {
                unsigned t[4], u[4];
                ldsm4(t, sW + bufo + bOff + (size_t)p * 16 * WST + kk);
                ldsm4(u, sW + bufo + 256 * WST + bOff + (size_t)p * 16 * WST + kk);
                unsigned bhA[2] = { t[0], t[1] }, bhB[2] = { t[2], t[3] };
                unsigned blA[2] = { u[0], u[1] }, blB[2] = { u[2], u[3] };
#pragma unroll
                for (int mt = 0; mt < 2; mt++) {
                    mma_bf16(acc[mt][2*p],   ah[mt], bhA);
                    mma_bf16(acc[mt][2*p],   al[mt], bhA);
                    mma_bf16(acc[mt][2*p],   ah[mt], blA);
                    mma_bf16(acc[mt][2*p+1], ah[mt], bhB);
                    mma_bf16(acc[mt][2*p+1], al[mt], bhB);
                    mma_bf16(acc[mt][2*p+1], ah[mt], blB);
                }
            }
        }
        if (ck < 7) { CP_WAIT0(); }
        __syncthreads();
    }

    // ---- residual: u = x1 + ff + b2 -> utmp (W region now free) ----
#pragma unroll
    for (int mt = 0; mt < 2; mt++) {
        int r0 = mbase + mt * 16 + g;
#pragma unroll
        for (int nt = 0; nt < 4; nt++) {
            int col = wn * 32 + nt * 8 + tq * 2;
            float bb0 = b2[col], bb1 = b2[col + 1];
            unsigned xh = *(const unsigned*)(x1hi + (size_t)r0 * XST + col);
            unsigned xl = *(const unsigned*)(x1lo + (size_t)r0 * XST + col);
            float x0 = __uint_as_float(xh << 16) + __uint_as_float(xl << 16);
            float x1v = __uint_as_float(xh & 0xffff0000u) + __uint_as_float(xl & 0xffff0000u);
            *(float2*)(utmp + (size_t)r0 * VST + col) =
                make_float2(x0 + acc[mt][nt][0] + bb0, x1v + acc[mt][nt][1] + bb1);
            unsigned yh = *(const unsigned*)(x1hi + (size_t)(r0 + 8) * XST + col);
            unsigned yl = *(const unsigned*)(x1lo + (size_t)(r0 + 8) * XST + col);
            float y0 = __uint_as_float(yh << 16) + __uint_as_float(yl << 16);
            float y1 = __uint_as_float(yh & 0xffff0000u) + __uint_as_float(yl & 0xffff0000u);
            *(float2*)(utmp + (size_t)(r0 + 8) * VST + col) =
                make_float2(y0 + acc[mt][nt][2] + bb0, y1 + acc[mt][nt][3] + bb1);
        }
    }
    __syncthreads();

    // ---- final LN -> out_x (8 threads per row) ----
    {
        int r = tid >> 3, q = tid & 7;
        float s1 = 0.f;
#pragma unroll
        for (int i = 0; i < 8; i++) {
            int col = q * 32 + i * 4;
            float4 v = *(float4*)(utmp + (size_t)r * VST + col);
            s1 += v.x + v.y + v.z + v.w;
        }
        s1 += __shfl_xor_sync(0xffffffffu, s1, 1);
        s1 += __shfl_xor_sync(0xffffffffu, s1, 2);
        s1 += __shfl_xor_sync(0xffffffffu, s1, 4);
        float mean = s1 * (1.f / 256.f);
        float s2 = 0.f;
#pragma unroll
        for (int i = 0; i < 8; i++) {
            int col = q * 32 + i * 4;
            float4 v = *(float4*)(utmp + (size_t)r * VST + col);
            float dx = v.x - mean, dy = v.y - mean, dz = v.z - mean, dw = v.w - mean;
            s2 += dx * dx + dy * dy + dz * dz + dw * dw;
        }
        s2 += __shfl_xor_sync(0xffffffffu, s2, 1);
        s2 += __shfl_xor_sync(0xffffffffu, s2, 2);
        s2 += __shfl_xor_sync(0xffffffffu, s2, 4);
        float rstd = rsqrtf(s2 * (1.f / 256.f) + 1e-5f);
        float* orow = out_x + (size_t)(m0 + r) * 256;
#pragma unroll
        for (int i = 0; i < 8; i++) {
            int col = q * 32 + i * 4;
            float4 v = *(float4*)(utmp + (size_t)r * VST + col);
            float4 gg = *(const float4*)(g2 + col);
            float4 bb = *(const float4*)(be2 + col);
            float4 o4;
            o4.x = (v.x - mean) * rstd * gg.x + bb.x;
            o4.y = (v.y - mean) * rstd * gg.y + bb.y;
            o4.z = (v.z - mean) * rstd * gg.z + bb.z;
            o4.w = (v.w - mean) * rstd * gg.w + bb.w;
            *(float4*)(orow + col) = o4;
        }
    }
}

// ---------------- fused CLS readout tail ----------------------------------
__device__ __forceinline__ float blk_sum256(float v, float* red, int h, int lane) {
#pragma unroll
    for (int o = 16; o; o >>= 1) v += __shfl_xor_sync(0xffffffffu, v, o);
    if (lane == 0) red[h] = v;
    __syncthreads();
    float t = 0.f;
#pragma unroll
    for (int i = 0; i < 8; i++) t += red[i];
    __syncthreads();
    return t;
}

__global__ void __launch_bounds__(256)
cls_tail(const float* __restrict__ CLS, const float* __restrict__ rkv,
         const unsigned char* __restrict__ cmask,
         const float* __restrict__ ro_w1, const float* __restrict__ ro_b1,
         const float* __restrict__ ro_w2, const float* __restrict__ ro_b2,
         const float* __restrict__ rg1, const float* __restrict__ rbe1,
         const float* __restrict__ rg2, const float* __restrict__ rbe2,
         float* __restrict__ out_c) {
    int b = blockIdx.x, tid = threadIdx.x, h = tid >> 5, lane = tid & 31;
    __shared__ float sq[256], c1s[256], h1s[256], red[8];
    __shared__ float sp[8 * 160];

    float clsv = CLS[(size_t)b * 256 + tid];
    sq[tid] = clsv;
    __syncthreads();

    const float scale = 0.17677669529663687f;
    const float* sqh = sq + h * 32;
    float svals[5];
    float smax = -INFINITY;
#pragma unroll
    for (int j = 0; j < 5; j++) {
        int m = lane + j * 32;
        float s = -INFINITY;
        if (m < NT) {
            const float* kr = rkv + (size_t)(b * NT + m) * 512 + h * 32;
            float s0 = 0.f;
#pragma unroll
            for (int d = 0; d < 32; d++) s0 = fmaf(sqh[d], kr[d], s0);
            s = s0 * scale;
            if (cmask[(size_t)b * NT + m]) s = -INFINITY;
        }
        svals[j] = s;
        smax = fmaxf(smax, s);
    }
#pragma unroll
    for (int o = 16; o; o >>= 1)
        smax = fmaxf(smax, __shfl_xor_sync(0xffffffffu, smax, o));
    float ssum = 0.f;
#pragma unroll
    for (int j = 0; j < 5; j++) {
        float p = __expf(svals[j] - smax);
        ssum += p;
        sp[h * 160 + lane + j * 32] = p;
    }
#pragma unroll
    for (int o = 16; o; o >>= 1)
        ssum += __shfl_xor_sync(0xffffffffu, ssum, o);
    __syncwarp();
    float inv = 1.f / ssum;
    float acc = 0.f;
    for (int m = 0; m < NT; m++)
        acc = fmaf(sp[h * 160 + m],
                   rkv[(size_t)(b * NT + m) * 512 + 256 + h * 32 + lane], acc);
    float v = clsv + acc * inv;
    __syncthreads();

    float mean = blk_sum256(v, red, h, lane) * (1.f / 256.f);
    float d = v - mean;
    float var = blk_sum256(d * d, red, h, lane) * (1.f / 256.f);
    float c1 = d * rsqrtf(var + 1e-5f) * rg1[tid] + rbe1[tid];
    c1s[tid] = c1;
    __syncthreads();

    {
        float a2 = 0.f;
        const float4* wr = (const float4*)(ro_w1 + (size_t)tid * 256);
#pragma unroll 8
        for (int i = 0; i < 64; i++) {
            float4 w = wr[i];
            float4 cc = *(const float4*)(c1s + i * 4);
            a2 = fmaf(w.x, cc.x, fmaf(w.y, cc.y, fmaf(w.z, cc.z, fmaf(w.w, cc.w, a2))));
        }
        h1s[tid] = fmaxf(a2 + ro_b1[tid], 0.f);
    }
    __syncthreads();

    float u;
    {
        float a2 = 0.f;
        const float4* wr = (const float4*)(ro_w2 + (size_t)tid * 256);
#pragma unroll 8
        for (int i = 0; i < 64; i++) {
            float4 w = wr[i];
            float4 cc = *(const float4*)(h1s + i * 4);
            a2 = fmaf(w.x, cc.x, fmaf(w.y, cc.y, fmaf(w.z, cc.z, fmaf(w.w, cc.w, a2))));
        }
        u = c1 + a2 + ro_b2[tid];
    }
    float mean2 = blk_sum256(u, red, h, lane) * (1.f / 256.f);
    float d2 = u - mean2;
    float var2 = blk_sum256(d2 * d2, red, h, lane) * (1.f / 256.f);
    out_c[(size_t)b * 256 + tid] = d2 * rsqrtf(var2 + 1e-5f) * rg2[tid] + rbe2[tid];
}

// ---------------- launch --------------------------------------------------
extern "C" void kernel_launch(void* const* d_in, const int* in_sizes, int n_in,
                              void* d_out, int out_size) {
    const float* node_x   = (const float*)d_in[0];
    const float* edge_x   = (const float*)d_in[1];
    const float* CLS      = (const float*)d_in[2];
    const unsigned char* nmask = (const unsigned char*)d_in[3];
    const unsigned char* cmask = (const unsigned char*)d_in[4];
    const float* w_qkv    = (const float*)d_in[5];
    const float* b_qkv    = (const float*)d_in[6];
    const float* w_kve    = (const float*)d_in[7];
    const float* b_kve    = (const float*)d_in[8];
    const float* w1       = (const float*)d_in[9];
    const float* b1       = (const float*)d_in[10];
    const float* w2       = (const float*)d_in[11];
    const float* b2       = (const float*)d_in[12];
    const float* g1       = (const float*)d_in[13];
    const float* be1      = (const float*)d_in[14];
    const float* g2       = (const float*)d_in[15];
    const float* be2      = (const float*)d_in[16];
    const float* ro_w_kv  = (const float*)d_in[17];
    const float* ro_b_kv  = (const float*)d_in[18];
    const float* ro_w1    = (const float*)d_in[19];
    const float* ro_b1    = (const float*)d_in[20];
    const float* ro_w2    = (const float*)d_in[21];
    const float* ro_b2    = (const float*)d_in[22];
    const float* ro_g1    = (const float*)d_in[23];
    const float* ro_be1   = (const float*)d_in[24];
    const float* ro_g2    = (const float*)d_in[25];
    const float* ro_be2   = (const float*)d_in[26];

    float* out_x = (float*)d_out;
    float* out_c = out_x + (size_t)BB * NN * DD;

    float *p_qkv, *p_kve, *p_attn, *p_rkv;
    __nv_bfloat16 *whi, *wlo;
    cudaGetSymbolAddress((void**)&p_qkv,  g_qkv);
    cudaGetSymbolAddress((void**)&p_kve,  g_kve);
    cudaGetSymbolAddress((void**)&p_attn, g_attn);
    cudaGetSymbolAddress((void**)&p_rkv,  g_rkv);
    cudaGetSymbolAddress((void**)&whi,    g_whi);
    cudaGetSymbolAddress((void**)&wlo,    g_wlo);

    cudaFuncSetAttribute(gemm_mma<false, false, true >, cudaFuncAttributeMaxDynamicSharedMemorySize, GEMM_SMEM);
    cudaFuncSetAttribute(gemm_mma<false, true,  false>, cudaFuncAttributeMaxDynamicSharedMemorySize, GEMM_SMEM);
    cudaFuncSetAttribute(attn_flash, cudaFuncAttributeMaxDynamicSharedMemorySize, ATT2_SMEM);
    cudaFuncSetAttribute(ffn_fused, cudaFuncAttributeMaxDynamicSharedMemorySize, FFN_SMEM);

    // fused weight conversion
    conv_all<<<(W_CONV + 255) / 256, 256>>>(w_qkv, w_kve, w1, w2, ro_w_kv, whi, wlo);

    // projections: qkv + edge-kv in ONE dual-job launch (BM=64)
    gemm_mma<false, false, true><<<6 * 128 + 4 * 256, 256, GEMM_SMEM>>>(
        node_x, edge_x, whi + OFF_QKV, wlo + OFF_QKV, b_qkv, p_qkv, BB * NN, 768,
        whi + OFF_KVE, wlo + OFF_KVE, b_kve, p_kve, BB * EE, 512,
        6 * 128, 6, 4);

    // flash attention
    attn_flash<<<dim3(HH, BB), 256, ATT2_SMEM>>>(p_qkv, p_kve, nmask, p_attn);

    // fused FFN block (512 threads): LN + FFN(relu) + residual + LN -> out_x
    ffn_fused<<<BB * NN / 64, 512, FFN_SMEM>>>(
        node_x, p_attn,
        whi + OFF_W1, wlo + OFF_W1, whi + OFF_W2, wlo + OFF_W2,
        b1, b2, g1, be1, g2, be2, out_x);

    // readout: rkv = [CLS; x] @ ro_w_kv (CONCAT rows)
    gemm_mma<false, true, false><<<dim3(4, 129), 256, GEMM_SMEM>>>(
        out_x, CLS, whi + OFF_ROKV, wlo + OFF_ROKV, ro_b_kv, p_rkv, BB * NT, 512,
        nullptr, nullptr, nullptr, nullptr, 0, 0, 0, 0, 0);

    // fused CLS tail
    cls_tail<<<BB, 256>>>(CLS, p_rkv, cmask, ro_w1, ro_b1, ro_w2, ro_b2,
                          ro_g1, ro_be1, ro_g2, ro_be2, out_c);
}

// round 14
// speedup vs baseline: 1.0456x; 1.0456x over previous
#include <cuda_runtime.h>
#include <cuda_bf16.h>
#include <math.h>

// Shapes
#define BB   64
#define NN   128
#define EE   256
#define DD   256
#define HH   8
#define MT   384   // N + E
#define NT   129   // N + 1

// ---------------- scratch (device globals; no allocation) ----------------
__device__ float g_qkv [BB*NN*3*DD];
__device__ float g_kve [BB*EE*2*DD];
__device__ float g_attn[BB*NN*DD];
__device__ float g_rkv [BB*NT*2*DD];

// bf16 hi/lo weight buffers, layout [Nc][256] (k contiguous)
#define OFF_QKV   0
#define OFF_KVE   (OFF_QKV + 768*256)
#define OFF_W1    (OFF_KVE + 512*256)
#define OFF_W2    (OFF_W1  + 256*256)
#define OFF_ROKV  (OFF_W2  + 256*256)
#define W_CONV    (OFF_ROKV+ 512*256)
__device__ __nv_bfloat16 g_whi[W_CONV];
__device__ __nv_bfloat16 g_wlo[W_CONV];

// ---------------- fused weight conversion (one launch) -------------------
__global__ void conv_all(const float* __restrict__ w_qkv,
                         const float* __restrict__ w_kve,
                         const float* __restrict__ w1,
                         const float* __restrict__ w2,
                         const float* __restrict__ ro_w_kv,
                         __nv_bfloat16* __restrict__ hi,
                         __nv_bfloat16* __restrict__ lo) {
    int i = blockIdx.x * 256 + threadIdx.x;
    if (i >= W_CONV) return;
    const float* W; int Nc; bool direct; int off;
    if      (i < OFF_KVE ) { W = w_qkv;   Nc = 768; direct = false; off = OFF_QKV;  }
    else if (i < OFF_W1  ) { W = w_kve;   Nc = 512; direct = false; off = OFF_KVE;  }
    else if (i < OFF_W2  ) { W = w1;      Nc = 256; direct = true;  off = OFF_W1;   }
    else if (i < OFF_ROKV) { W = w2;      Nc = 256; direct = true;  off = OFF_W2;   }
    else                   { W = ro_w_kv; Nc = 512; direct = false; off = OFF_ROKV; }
    int li = i - off;
    int n = li >> 8, k = li & 255;
    float v = direct ? W[(size_t)n * 256 + k] : W[(size_t)k * Nc + n];
    __nv_bfloat16 h = __float2bfloat16(v);
    hi[i] = h;
    lo[i] = __float2bfloat16(v - __bfloat162float(h));
}

// ---------------- mma / ldmatrix / cp.async helpers -----------------------
__device__ __forceinline__ void mma_bf16(float* c, const unsigned* a, const unsigned* b) {
    asm volatile(
        "mma.sync.aligned.m16n8k16.row.col.f32.bf16.bf16.f32 "
        "{%0,%1,%2,%3}, {%4,%5,%6,%7}, {%8,%9}, {%0,%1,%2,%3};\n"
        : "+f"(c[0]), "+f"(c[1]), "+f"(c[2]), "+f"(c[3])
        : "r"(a[0]), "r"(a[1]), "r"(a[2]), "r"(a[3]), "r"(b[0]), "r"(b[1]));
}

__device__ __forceinline__ void ldsm4(unsigned* r, const void* p) {
    unsigned a = (unsigned)__cvta_generic_to_shared(p);
    asm volatile("ldmatrix.sync.aligned.m8n8.x4.shared.b16 {%0,%1,%2,%3}, [%4];"
                 : "=r"(r[0]), "=r"(r[1]), "=r"(r[2]), "=r"(r[3]) : "r"(a));
}

__device__ __forceinline__ void cpa16(void* s, const void* g) {
    unsigned a = (unsigned)__cvta_generic_to_shared(s);
    asm volatile("cp.async.cg.shared.global [%0], [%1], 16;" :: "r"(a), "l"(g));
}
#define CP_COMMIT() asm volatile("cp.async.commit_group;" ::: "memory")
#define CP_WAIT0()  asm volatile("cp.async.wait_group 0;" ::: "memory")

// packed-cvt hi/lo split: low half = x, high half = y
__device__ __forceinline__ void split2(float x, float y, unsigned& hi, unsigned& lo) {
    unsigned h;
    asm("cvt.rn.bf16x2.f32 %0, %1, %2;" : "=r"(h) : "f"(y), "f"(x));
    float fx = __uint_as_float(h << 16);
    float fy = __uint_as_float(h & 0xffff0000u);
    unsigned l;
    asm("cvt.rn.bf16x2.f32 %0, %1, %2;" : "=r"(l) : "f"(y - fy), "f"(x - fx));
    hi = h; lo = l;
}

#define GST 72   // smem row stride in bf16 (144B)
#define GEMM_SMEM ((2*64*GST + 4*128*GST) * (int)sizeof(__nv_bfloat16))   // 92160

// ---------------- bf16-split tensor-core GEMM (BM=64, pipelined) ----------
template<bool RELU, bool CONCAT, bool DUAL>
__global__ void __launch_bounds__(256)
gemm_mma(const float* __restrict__ A, const float* __restrict__ A2,
         const __nv_bfloat16* __restrict__ Whi,
         const __nv_bfloat16* __restrict__ Wlo,
         const float* __restrict__ bias,
         float* __restrict__ C, int M, int Nc,
         const __nv_bfloat16* Whi2, const __nv_bfloat16* Wlo2,
         const float* bias2, float* C2, int M2, int Nc2,
         int nb0, int gx0, int gx1) {
    extern __shared__ __nv_bfloat16 sm[];
    __nv_bfloat16* sAhi = sm;
    __nv_bfloat16* sAlo = sAhi + 64 * GST;
    __nv_bfloat16* sBhi = sAlo + 64 * GST;
    __nv_bfloat16* sBlo = sBhi + 2 * 128 * GST;

    int bx, by;
    const float* Ap = A;
    const __nv_bfloat16* Whip = Whi;
    const __nv_bfloat16* Wlop = Wlo;
    const float* biasp = bias;
    float* Cp = C;
    int Mp = M, Ncp = Nc;
    if (DUAL) {
        int bid = blockIdx.x;
        if (bid < nb0) { bx = bid % gx0; by = bid / gx0; }
        else {
            bid -= nb0; bx = bid % gx1; by = bid / gx1;
            Ap = A2; Whip = Whi2; Wlop = Wlo2; biasp = bias2; Cp = C2;
            Mp = M2; Ncp = Nc2;
        }
    } else {
        bx = blockIdx.x; by = blockIdx.y;
    }

    int tid = threadIdx.x;
    int lane = tid & 31, warp = tid >> 5;
    int g = lane >> 2, tq = lane & 3;
    int mbase = (warp >> 2) * 32;
    int nbase = (warp & 3) * 32;
    int m0 = by * 64;
    int n0 = bx * 128;

    int lr = lane & 7, sel = lane >> 3;
    const __nv_bfloat16* aHiB = sAhi + (size_t)(mbase + (sel & 1) * 8 + lr) * GST + ((sel >> 1) & 1) * 8;
    const __nv_bfloat16* aLoB = sAlo + (size_t)(mbase + (sel & 1) * 8 + lr) * GST + ((sel >> 1) & 1) * 8;
    size_t bOff = (size_t)(nbase + (sel >> 1) * 8 + lr) * GST + (sel & 1) * 8;

    int ar = tid >> 2, aq = tid & 3;
    int arr = m0 + ar;
    bool avalid = arr < Mp;
    const float* aRow;
    if (CONCAT) {
        int bidx = arr / NT, t = arr - bidx * NT;
        aRow = (t == 0) ? A2 + (size_t)bidx * 256
                        : Ap + (size_t)(bidx * NN + t - 1) * 256;
    } else {
        aRow = Ap + (size_t)arr * 256;
    }
    int colb = aq * 16;
    aRow += colb;

    int bn = tid >> 1, bck = (tid & 1) * 32;

    float acc[2][4][4];
#pragma unroll
    for (int mt = 0; mt < 2; mt++)
#pragma unroll
        for (int nt = 0; nt < 4; nt++)
#pragma unroll
            for (int i = 0; i < 4; i++) acc[mt][nt][i] = 0.f;

    float4 av[4];
    {
        const __nv_bfloat16* wh = Whip + (size_t)(n0 + bn) * 256 + bck;
        const __nv_bfloat16* wl = Wlop + (size_t)(n0 + bn) * 256 + bck;
        __nv_bfloat16* dh = sBhi + (size_t)bn * GST + bck;
        __nv_bfloat16* dl = sBlo + (size_t)bn * GST + bck;
#pragma unroll
        for (int i = 0; i < 4; i++) {
            cpa16(dh + i * 8, wh + i * 8);
            cpa16(dl + i * 8, wl + i * 8);
        }
        CP_COMMIT();
#pragma unroll
        for (int i = 0; i < 4; i++)
            av[i] = avalid ? *(const float4*)(aRow + i * 4)
                           : make_float4(0.f, 0.f, 0.f, 0.f);
#pragma unroll
        for (int i = 0; i < 4; i++) {
            unsigned h01, l01, h23, l23;
            split2(av[i].x, av[i].y, h01, l01);
            split2(av[i].z, av[i].w, h23, l23);
            int c = colb + i * 4;
            *(unsigned*)(sAhi + (size_t)ar * GST + c)     = h01;
            *(unsigned*)(sAhi + (size_t)ar * GST + c + 2) = h23;
            *(unsigned*)(sAlo + (size_t)ar * GST + c)     = l01;
            *(unsigned*)(sAlo + (size_t)ar * GST + c + 2) = l23;
        }
        CP_WAIT0();
        __syncthreads();
    }

    for (int it = 0; it < 4; it++) {
        int nk = it + 1;
        if (nk < 4) {
            int buf = nk & 1;
            const __nv_bfloat16* wh = Whip + (size_t)(n0 + bn) * 256 + nk * 64 + bck;
            const __nv_bfloat16* wl = Wlop + (size_t)(n0 + bn) * 256 + nk * 64 + bck;
            __nv_bfloat16* dh = sBhi + (size_t)buf * 128 * GST + (size_t)bn * GST + bck;
            __nv_bfloat16* dl = sBlo + (size_t)buf * 128 * GST + (size_t)bn * GST + bck;
#pragma unroll
            for (int i = 0; i < 4; i++) {
                cpa16(dh + i * 8, wh + i * 8);
                cpa16(dl + i * 8, wl + i * 8);
            }
            CP_COMMIT();
#pragma unroll
            for (int i = 0; i < 4; i++)
                av[i] = avalid ? *(const float4*)(aRow + nk * 64 + i * 4)
                               : make_float4(0.f, 0.f, 0.f, 0.f);
        }

        {
            size_t bufo = (size_t)(it & 1) * 128 * GST;
            const __nv_bfloat16* bHiB = sBhi + bufo + bOff;
            const __nv_bfloat16* bLoB = sBlo + bufo + bOff;
#pragma unroll
            for (int kk = 0; kk < 64; kk += 16) {
                unsigned ah[2][4], al[2][4], bh[4][2], bl[4][2];
#pragma unroll
                for (int mt = 0; mt < 2; mt++) {
                    ldsm4(ah[mt], aHiB + (size_t)mt * 16 * GST + kk);
                    ldsm4(al[mt], aLoB + (size_t)mt * 16 * GST + kk);
                }
#pragma unroll
                for (int p = 0; p < 2; p++) {
                    unsigned t[4];
                    ldsm4(t, bHiB + (size_t)p * 16 * GST + kk);
                    bh[2*p][0] = t[0]; bh[2*p][1] = t[1];
                    bh[2*p+1][0] = t[2]; bh[2*p+1][1] = t[3];
                    ldsm4(t, bLoB + (size_t)p * 16 * GST + kk);
                    bl[2*p][0] = t[0]; bl[2*p][1] = t[1];
                    bl[2*p+1][0] = t[2]; bl[2*p+1][1] = t[3];
                }
#pragma unroll
                for (int mt = 0; mt < 2; mt++)
#pragma unroll
                    for (int nt = 0; nt < 4; nt++) {
                        mma_bf16(acc[mt][nt], ah[mt], bh[nt]);
                        mma_bf16(acc[mt][nt], al[mt], bh[nt]);
                        mma_bf16(acc[mt][nt], ah[mt], bl[nt]);
                    }
            }
        }
        __syncthreads();
        if (nk < 4) {
#pragma unroll
            for (int i = 0; i < 4; i++) {
                unsigned h01, l01, h23, l23;
                split2(av[i].x, av[i].y, h01, l01);
                split2(av[i].z, av[i].w, h23, l23);
                int c = colb + i * 4;
                *(unsigned*)(sAhi + (size_t)ar * GST + c)     = h01;
                *(unsigned*)(sAhi + (size_t)ar * GST + c + 2) = h23;
                *(unsigned*)(sAlo + (size_t)ar * GST + c)     = l01;
                *(unsigned*)(sAlo + (size_t)ar * GST + c + 2) = l23;
            }
            CP_WAIT0();
            __syncthreads();
        }
    }

#pragma unroll
    for (int mt = 0; mt < 2; mt++) {
        int r0 = m0 + mbase + mt * 16 + g;
#pragma unroll
        for (int nt = 0; nt < 4; nt++) {
            int col = n0 + nbase + nt * 8 + tq * 2;
            float b0 = biasp[col], b1 = biasp[col + 1];
            if (r0 < Mp) {
                float v0 = acc[mt][nt][0] + b0;
                float v1 = acc[mt][nt][1] + b1;
                if (RELU) { v0 = fmaxf(v0, 0.f); v1 = fmaxf(v1, 0.f); }
                Cp[(size_t)r0 * Ncp + col]     = v0;
                Cp[(size_t)r0 * Ncp + col + 1] = v1;
            }
            if (r0 + 8 < Mp) {
                float v2 = acc[mt][nt][2] + b0;
                float v3 = acc[mt][nt][3] + b1;
                if (RELU) { v2 = fmaxf(v2, 0.f); v3 = fmaxf(v3, 0.f); }
                Cp[(size_t)(r0 + 8) * Ncp + col]     = v2;
                Cp[(size_t)(r0 + 8) * Ncp + col + 1] = v3;
            }
        }
    }
}

// ---------------- flash attention on tensor cores -------------------------
#define AK_STR 40
#define AV_STR 392
#define ATT2_SMEM ((384*AK_STR + 2*32*AV_STR) * (int)sizeof(__nv_bfloat16))

__global__ void __launch_bounds__(256, 2)
attn_flash(const float* __restrict__ qkv,
           const float* __restrict__ kve,
           const unsigned char* __restrict__ nmask,
           float* __restrict__ out) {
    int h = blockIdx.x, b = blockIdx.y;
    extern __shared__ __nv_bfloat16 smb[];
    __nv_bfloat16* Khi  = smb;
    __nv_bfloat16* Vthi = Khi  + 384 * AK_STR;
    __nv_bfloat16* Vtlo = Vthi + 32 * AV_STR;

    int tid = threadIdx.x;
    // vectorized staging: each thread handles 4 consecutive d of one token
    for (int idx = tid; idx < MT * 8; idx += 256) {
        int m = idx >> 3, d4 = (idx & 7) * 4;
        float4 kv4, vv4;
        if (m < NN) {
            const float* base = qkv + (size_t)(b * NN + m) * 768 + h * 32 + d4;
            kv4 = *(const float4*)(base + 256);
            vv4 = *(const float4*)(base + 512);
        } else {
            const float* base = kve + (size_t)(b * EE + (m - NN)) * 512 + h * 32 + d4;
            kv4 = *(const float4*)(base);
            vv4 = *(const float4*)(base + 256);
        }
        // K: packed bf16 stores (no lo kept)
        unsigned kh01, kh23;
        asm("cvt.rn.bf16x2.f32 %0, %1, %2;" : "=r"(kh01) : "f"(kv4.y), "f"(kv4.x));
        asm("cvt.rn.bf16x2.f32 %0, %1, %2;" : "=r"(kh23) : "f"(kv4.w), "f"(kv4.z));
        *(unsigned*)(Khi + m * AK_STR + d4)     = kh01;
        *(unsigned*)(Khi + m * AK_STR + d4 + 2) = kh23;
        // V transposed: scalar stores (hi + lo)
        float vs[4] = { vv4.x, vv4.y, vv4.z, vv4.w };
#pragma unroll
        for (int j = 0; j < 4; j++) {
            __nv_bfloat16 vh = __float2bfloat16(vs[j]);
            Vthi[(d4 + j) * AV_STR + m] = vh;
            Vtlo[(d4 + j) * AV_STR + m] = __float2bfloat16(vs[j] - __bfloat162float(vh));
        }
    }
    __syncthreads();

    int lane = tid & 31, warp = tid >> 5;
    int g = lane >> 2, tq = lane & 3;
    int lr = lane & 7, sel = lane >> 3;
    int r0 = warp * 16 + g;
    int r1 = r0 + 8;
    const float scale = 0.17677669529663687f;

    const __nv_bfloat16* kHiB = Khi  + (size_t)((sel >> 1) * 8 + lr) * AK_STR + (sel & 1) * 8;
    const __nv_bfloat16* vHiB = Vthi + (size_t)((sel >> 1) * 8 + lr) * AV_STR + (sel & 1) * 8;
    const __nv_bfloat16* vLoB = Vtlo + (size_t)((sel >> 1) * 8 + lr) * AV_STR + (sel & 1) * 8;

    unsigned qh[2][4], ql[2][4];
    {
        const float* q0p = qkv + (size_t)(b * NN + r0) * 768 + h * 32;
        const float* q1p = qkv + (size_t)(b * NN + r1) * 768 + h * 32;
#pragma unroll
        for (int kk2 = 0; kk2 < 2; kk2++) {
            int kb = kk2 * 16 + tq * 2;
            float2 v;
            v = *(const float2*)(q0p + kb);
            split2(v.x * scale, v.y * scale, qh[kk2][0], ql[kk2][0]);
            v = *(const float2*)(q1p + kb);
            split2(v.x * scale, v.y * scale, qh[kk2][1], ql[kk2][1]);
            v = *(const float2*)(q0p + kb + 8);
            split2(v.x * scale, v.y * scale, qh[kk2][2], ql[kk2][2]);
            v = *(const float2*)(q1p + kb + 8);
            split2(v.x * scale, v.y * scale, qh[kk2][3], ql[kk2][3]);
        }
    }

    const unsigned short* mrow0 =
        (const unsigned short*)(nmask + (size_t)(b * NN + r0) * MT);
    const unsigned short* mrow1 =
        (const unsigned short*)(nmask + (size_t)(b * NN + r1) * MT);

    float m0 = -INFINITY, m1 = -INFINITY, l0 = 0.f, l1 = 0.f;
    float o[4][4];
#pragma unroll
    for (int nt = 0; nt < 4; nt++)
#pragma unroll
        for (int i = 0; i < 4; i++) o[nt][i] = 0.f;

#pragma unroll
    for (int c = 0; c < 6; c++) {
        int tkb = c * 64;
        float s[8][4];
#pragma unroll
        for (int nt = 0; nt < 8; nt++)
#pragma unroll
            for (int i = 0; i < 4; i++) s[nt][i] = 0.f;

#pragma unroll
        for (int kk2 = 0; kk2 < 2; kk2++) {
#pragma unroll
            for (int p = 0; p < 4; p++) {
                unsigned t[4];
                ldsm4(t, kHiB + (size_t)(tkb + p * 16) * AK_STR + kk2 * 16);
                unsigned bhA[2] = { t[0], t[1] }, bhB[2] = { t[2], t[3] };
                mma_bf16(s[2*p],   qh[kk2], bhA);
                mma_bf16(s[2*p],   ql[kk2], bhA);
                mma_bf16(s[2*p+1], qh[kk2], bhB);
                mma_bf16(s[2*p+1], ql[kk2], bhB);
            }
        }

        float cm0 = -INFINITY, cm1 = -INFINITY;
#pragma unroll
        for (int nt = 0; nt < 8; nt++) {
            int t = tkb + nt * 8 + tq * 2;
            unsigned short mm0 = mrow0[t >> 1];
            unsigned short mm1 = mrow1[t >> 1];
            if (mm0 & 0x00FFu) s[nt][0] = -INFINITY;
            if (mm0 & 0xFF00u) s[nt][1] = -INFINITY;
            if (mm1 & 0x00FFu) s[nt][2] = -INFINITY;
            if (mm1 & 0xFF00u) s[nt][3] = -INFINITY;
            cm0 = fmaxf(cm0, fmaxf(s[nt][0], s[nt][1]));
            cm1 = fmaxf(cm1, fmaxf(s[nt][2], s[nt][3]));
        }
        cm0 = fmaxf(cm0, __shfl_xor_sync(0xffffffffu, cm0, 1));
        cm0 = fmaxf(cm0, __shfl_xor_sync(0xffffffffu, cm0, 2));
        cm1 = fmaxf(cm1, __shfl_xor_sync(0xffffffffu, cm1, 1));
        cm1 = fmaxf(cm1, __shfl_xor_sync(0xffffffffu, cm1, 2));

        float nm0 = fmaxf(m0, cm0), nm1 = fmaxf(m1, cm1);
        float corr0 = (m0 == -INFINITY) ? 0.f : __expf(m0 - nm0);
        float corr1 = (m1 == -INFINITY) ? 0.f : __expf(m1 - nm1);
        float e0 = (nm0 == -INFINITY) ? 0.f : nm0;
        float e1 = (nm1 == -INFINITY) ? 0.f : nm1;
        m0 = nm0; m1 = nm1;
        l0 *= corr0; l1 *= corr1;
#pragma unroll
        for (int nt = 0; nt < 4; nt++) {
            o[nt][0] *= corr0; o[nt][1] *= corr0;
            o[nt][2] *= corr1; o[nt][3] *= corr1;
        }

#pragma unroll
        for (int ks = 0; ks < 4; ks++) {
            float p00 = __expf(s[2*ks][0]   - e0);
            float p01 = __expf(s[2*ks][1]   - e0);
            float p02 = __expf(s[2*ks][2]   - e1);
            float p03 = __expf(s[2*ks][3]   - e1);
            float p10 = __expf(s[2*ks+1][0] - e0);
            float p11 = __expf(s[2*ks+1][1] - e0);
            float p12 = __expf(s[2*ks+1][2] - e1);
            float p13 = __expf(s[2*ks+1][3] - e1);
            l0 += p00 + p01 + p10 + p11;
            l1 += p02 + p03 + p12 + p13;
            unsigned ah[4], al[4];
            split2(p00, p01, ah[0], al[0]);
            split2(p02, p03, ah[1], al[1]);
            split2(p10, p11, ah[2], al[2]);
            split2(p12, p13, ah[3], al[3]);
#pragma unroll
            for (int p = 0; p < 2; p++) {
                unsigned t[4], u[4];
                ldsm4(t, vHiB + (size_t)p * 16 * AV_STR + tkb + ks * 16);
                ldsm4(u, vLoB + (size_t)p * 16 * AV_STR + tkb + ks * 16);
                unsigned bhA[2] = { t[0], t[1] }, bhB[2] = { t[2], t[3] };
                unsigned blA[2] = { u[0], u[1] }, blB[2] = { u[2], u[3] };
                mma_bf16(o[2*p],   ah, bhA);
                mma_bf16(o[2*p],   al, bhA);
                mma_bf16(o[2*p],   ah, blA);
                mma_bf16(o[2*p+1], ah, bhB);
                mma_bf16(o[2*p+1], al, bhB);
                mma_bf16(o[2*p+1], ah, blB);
            }
        }
    }

    l0 += __shfl_xor_sync(0xffffffffu, l0, 1);
    l0 += __shfl_xor_sync(0xffffffffu, l0, 2);
    l1 += __shfl_xor_sync(0xffffffffu, l1, 1);
    l1 += __shfl_xor_sync(0xffffffffu, l1, 2);
    float inv0 = 1.f / l0, inv1 = 1.f / l1;
    size_t ob0 = (size_t)(b * NN + r0) * DD + h * 32;
    size_t ob1 = (size_t)(b * NN + r1) * DD + h * 32;
#pragma unroll
    for (int nt = 0; nt < 4; nt++) {
        int dcol = nt * 8 + tq * 2;
        *(float2*)(out + ob0 + dcol) = make_float2(o[nt][0] * inv0, o[nt][1] * inv0);
        *(float2*)(out + ob1 + dcol) = make_float2(o[nt][2] * inv1, o[nt][3] * inv1);
    }
}

// ---------------- fused FFN megakernel (256 threads — Round-11 proven) ----
#define XST 264   // x1/h1 row stride in bf16
#define WST 40    // W chunk row stride in bf16 (KC=32 + pad)
#define VST 260   // fp32 temp row stride
#define FFN_SMEM ((4*64*XST + 2*2*256*WST) * (int)sizeof(__nv_bfloat16))  // 217088

__global__ void __launch_bounds__(256)
ffn_fused(const float* __restrict__ nx, const float* __restrict__ at,
          const __nv_bfloat16* __restrict__ w1hi, const __nv_bfloat16* __restrict__ w1lo,
          const __nv_bfloat16* __restrict__ w2hi, const __nv_bfloat16* __restrict__ w2lo,
          const float* __restrict__ b1, const float* __restrict__ b2,
          const float* __restrict__ g1, const float* __restrict__ be1,
          const float* __restrict__ g2, const float* __restrict__ be2,
          float* __restrict__ out_x) {
    extern __shared__ __nv_bfloat16 sm[];
    __nv_bfloat16* x1hi = sm;
    __nv_bfloat16* x1lo = x1hi + 64 * XST;
    __nv_bfloat16* h1hi = x1lo + 64 * XST;
    __nv_bfloat16* h1lo = h1hi + 64 * XST;
    __nv_bfloat16* sW   = h1lo + 64 * XST;      // [buf][hi/lo][256][WST]
    float* vtmp = (float*)h1hi;                  // phase-0 temp (64xVST)
    float* utmp = (float*)sW;                    // final temp   (64xVST)

    int tid = threadIdx.x;
    int lane = tid & 31, warp = tid >> 5;
    int g = lane >> 2, tq = lane & 3;
    int lr = lane & 7, sel = lane >> 3;
    int mbase = (warp >> 2) * 32;
    int nwarp = warp & 3;
    int m0 = blockIdx.x * 64;

    // ---- issue W1 chunk0 early (hides under phase 0) ----
    {
        const __nv_bfloat16* wh = w1hi + (size_t)tid * 256;
        const __nv_bfloat16* wl = w1lo + (size_t)tid * 256;
        __nv_bfloat16* dh = sW + (size_t)tid * WST;
        __nv_bfloat16* dl = sW + 256 * WST + (size_t)tid * WST;
#pragma unroll
        for (int i = 0; i < 4; i++) { cpa16(dh + i * 8, wh + i * 8); cpa16(dl + i * 8, wl + i * 8); }
        CP_COMMIT();
    }

    // ---- phase 0: x1 = LN(node_x + attn) ----
    {
        int r = tid >> 2, q = tid & 3;
        const float* nrow = nx + (size_t)(m0 + r) * 256;
        const float* arow = at + (size_t)(m0 + r) * 256;
        float s1 = 0.f;
#pragma unroll
        for (int i = 0; i < 16; i++) {
            int col = i * 16 + q * 4;
            float4 v = *(const float4*)(nrow + col);
            float4 a = *(const float4*)(arow + col);
            v.x += a.x; v.y += a.y; v.z += a.z; v.w += a.w;
            *(float4*)(vtmp + (size_t)r * VST + col) = v;
            s1 += v.x + v.y + v.z + v.w;
        }
        s1 += __shfl_xor_sync(0xffffffffu, s1, 1);
        s1 += __shfl_xor_sync(0xffffffffu, s1, 2);
        float mean = s1 * (1.f / 256.f);
        float s2 = 0.f;
#pragma unroll
        for (int i = 0; i < 16; i++) {
            int col = i * 16 + q * 4;
            float4 v = *(float4*)(vtmp + (size_t)r * VST + col);
            v.x -= mean; v.y -= mean; v.z -= mean; v.w -= mean;
            *(float4*)(vtmp + (size_t)r * VST + col) = v;
            s2 += v.x * v.x + v.y * v.y + v.z * v.z + v.w * v.w;
        }
        s2 += __shfl_xor_sync(0xffffffffu, s2, 1);
        s2 += __shfl_xor_sync(0xffffffffu, s2, 2);
        float rstd = rsqrtf(s2 * (1.f / 256.f) + 1e-5f);
#pragma unroll
        for (int i = 0; i < 16; i++) {
            int col = i * 16 + q * 4;
            float4 v = *(float4*)(vtmp + (size_t)r * VST + col);
            float4 gg = *(const float4*)(g1 + col);
            float4 bb = *(const float4*)(be1 + col);
            float x0 = v.x * rstd * gg.x + bb.x;
            float x1 = v.y * rstd * gg.y + bb.y;
            float x2 = v.z * rstd * gg.z + bb.z;
            float x3 = v.w * rstd * gg.w + bb.w;
            unsigned h01, l01, h23, l23;
            split2(x0, x1, h01, l01);
            split2(x2, x3, h23, l23);
            *(unsigned*)(x1hi + (size_t)r * XST + col)     = h01;
            *(unsigned*)(x1hi + (size_t)r * XST + col + 2) = h23;
            *(unsigned*)(x1lo + (size_t)r * XST + col)     = l01;
            *(unsigned*)(x1lo + (size_t)r * XST + col + 2) = l23;
        }
    }
    CP_WAIT0();
    __syncthreads();

    // frag base pointers
    const __nv_bfloat16* a1HiB = x1hi + (size_t)(mbase + (sel & 1) * 8 + lr) * XST + ((sel >> 1) & 1) * 8;
    const __nv_bfloat16* a1LoB = x1lo + (size_t)(mbase + (sel & 1) * 8 + lr) * XST + ((sel >> 1) & 1) * 8;
    const __nv_bfloat16* a2HiB = h1hi + (size_t)(mbase + (sel & 1) * 8 + lr) * XST + ((sel >> 1) & 1) * 8;
    const __nv_bfloat16* a2LoB = h1lo + (size_t)(mbase + (sel & 1) * 8 + lr) * XST + ((sel >> 1) & 1) * 8;
    size_t bOff = (size_t)(nwarp * 64 + (sel >> 1) * 8 + lr) * WST + (sel & 1) * 8;

    float acc[2][8][4];
#pragma unroll
    for (int mt = 0; mt < 2; mt++)
#pragma unroll
        for (int nt = 0; nt < 8; nt++)
#pragma unroll
            for (int i = 0; i < 4; i++) acc[mt][nt][i] = 0.f;

    // ---- GEMM1: h1 = relu(x1 @ W1^T + b1), KC=32 double-buffered ----
#pragma unroll
    for (int ck = 0; ck < 8; ck++) {
        if (ck < 7) {
            int buf = (ck + 1) & 1;
            const __nv_bfloat16* wh = w1hi + (size_t)tid * 256 + (ck + 1) * 32;
            const __nv_bfloat16* wl = w1lo + (size_t)tid * 256 + (ck + 1) * 32;
            __nv_bfloat16* dh = sW + (size_t)buf * 2 * 256 * WST + (size_t)tid * WST;
            __nv_bfloat16* dl = dh + 256 * WST;
#pragma unroll
            for (int i = 0; i < 4; i++) { cpa16(dh + i * 8, wh + i * 8); cpa16(dl + i * 8, wl + i * 8); }
            CP_COMMIT();
        }
        size_t bufo = (size_t)(ck & 1) * 2 * 256 * WST;
#pragma unroll
        for (int kk = 0; kk < 32; kk += 16) {
            unsigned ah[2][4], al[2][4];
#pragma unroll
            for (int mt = 0; mt < 2; mt++) {
                ldsm4(ah[mt], a1HiB + (size_t)mt * 16 * XST + ck * 32 + kk);
                ldsm4(al[mt], a1LoB + (size_t)mt * 16 * XST + ck * 32 + kk);
            }
#pragma unroll
            for (int p = 0; p < 4; p++) {
                unsigned t[4], u[4];
                ldsm4(t, sW + bufo + bOff + (size_t)p * 16 * WST + kk);
                ldsm4(u, sW + bufo + 256 * WST + bOff + (size_t)p * 16 * WST + kk);
                unsigned bhA[2] = { t[0], t[1] }, bhB[2] = { t[2], t[3] };
                unsigned blA[2] = { u[0], u[1] }, blB[2] = { u[2], u[3] };
#pragma unroll
                for (int mt = 0; mt < 2; mt++) {
                    mma_bf16(acc[mt][2*p],   ah[mt], bhA);
                    mma_bf16(acc[mt][2*p],   al[mt], bhA);
                    mma_bf16(acc[mt][2*p],   ah[mt], blA);
                    mma_bf16(acc[mt][2*p+1], ah[mt], bhB);
                    mma_bf16(acc[mt][2*p+1], al[mt], bhB);
                    mma_bf16(acc[mt][2*p+1], ah[mt], blB);
                }
            }
        }
        if (ck < 7) { CP_WAIT0(); }
        __syncthreads();
    }

    // issue W2 chunk0 (into buf0, safe: last read of buf0 was ck=6)
    {
        const __nv_bfloat16* wh = w2hi + (size_t)tid * 256;
        const __nv_bfloat16* wl = w2lo + (size_t)tid * 256;
        __nv_bfloat16* dh = sW + (size_t)tid * WST;
        __nv_bfloat16* dl = sW + 256 * WST + (size_t)tid * WST;
#pragma unroll
        for (int i = 0; i < 4; i++) { cpa16(dh + i * 8, wh + i * 8); cpa16(dl + i * 8, wl + i * 8); }
        CP_COMMIT();
    }

    // epilogue1: h1 = relu(acc + b1) -> smem hi/lo; reset acc
#pragma unroll
    for (int mt = 0; mt < 2; mt++) {
        int r0 = mbase + mt * 16 + g;
#pragma unroll
        for (int nt = 0; nt < 8; nt++) {
            int col = nwarp * 64 + nt * 8 + tq * 2;
            float bb0 = b1[col], bb1 = b1[col + 1];
            float v0 = fmaxf(acc[mt][nt][0] + bb0, 0.f);
            float v1 = fmaxf(acc[mt][nt][1] + bb1, 0.f);
            float v2 = fmaxf(acc[mt][nt][2] + bb0, 0.f);
            float v3 = fmaxf(acc[mt][nt][3] + bb1, 0.f);
            unsigned h01, l01, h23, l23;
            split2(v0, v1, h01, l01);
            split2(v2, v3, h23, l23);
            *(unsigned*)(h1hi + (size_t)r0 * XST + col)       = h01;
            *(unsigned*)(h1lo + (size_t)r0 * XST + col)       = l01;
            *(unsigned*)(h1hi + (size_t)(r0 + 8) * XST + col) = h23;
            *(unsigned*)(h1lo + (size_t)(r0 + 8) * XST + col) = l23;
            acc[mt][nt][0] = 0.f; acc[mt][nt][1] = 0.f;
            acc[mt][nt][2] = 0.f; acc[mt][nt][3] = 0.f;
        }
    }
    CP_WAIT0();
    __syncthreads();

    // ---- GEMM2: ff = h1 @ W2^T ----
#pragma unroll
    for (int ck = 0; ck < 8; ck++) {
        if (ck < 7) {
            int buf = (ck + 1) & 1;
            const __nv_bfloat16* wh = w2hi + (size_t)tid * 256 + (ck + 1) * 32;
            const __nv_bfloat16* wl = w2lo + (size_t)tid * 256 + (ck + 1) * 32;
            __nv_bfloat16* dh = sW + (size_t)buf * 2 * 256 * WST + (size_t)tid * WST;
            __nv_bfloat16* dl = dh + 256 * WST;
#pragma unroll
            for (int i = 0; i < 4; i++) { cpa16(dh + i * 8, wh + i * 8); cpa16(dl + i * 8, wl + i * 8); }
            CP_COMMIT();
        }
        size_t bufo = (size_t)(ck & 1) * 2 * 256 * WST;
#pragma unroll
        for (int kk = 0; kk < 32; kk += 16) {
            unsigned ah[2][4], al[2][4];
#pragma unroll
            for (int mt = 0; mt < 2; mt++) {
                ldsm4(ah[mt], a2HiB + (size_t)mt * 16 * XST + ck * 32 + kk);
                ldsm4(al[mt], a2LoB + (size_t)mt * 16 * XST + ck * 32 + kk);
            }
#pragma unroll
            for (int p = 0; p < 4; p++) {
                unsigned t[4], u[4];
                ldsm4(t, sW + bufo + bOff + (size_t)p * 16 * WST + kk);
                ldsm4(u, sW + bufo + 256 * WST + bOff + (size_t)p * 16 * WST + kk);
                unsigned bhA[2] = { t[0], t[1] }, bhB[2] = { t[2], t[3] };
                unsigned blA[2] = { u[0], u[1] }, blB[2] = { u[2], u[3] };
#pragma unroll
                for (int mt = 0; mt < 2; mt++) {
                    mma_bf16(acc[mt][2*p],   ah[mt], bhA);
                    mma_bf16(acc[mt][2*p],   al[mt], bhA);
                    mma_bf16(acc[mt][2*p],   ah[mt], blA);
                    mma_bf16(acc[mt][2*p+1], ah[mt], bhB);
                    mma_bf16(acc[mt][2*p+1], al[mt], bhB);
                    mma_bf16(acc[mt][2*p+1], ah[mt], blB);
                }
            }
        }
        if (ck < 7) { CP_WAIT0(); }
        __syncthreads();
    }

    // ---- residual: u = x1 + ff + b2 -> utmp (W region now free) ----
#pragma unroll
    for (int mt = 0; mt < 2; mt++) {
        int r0 = mbase + mt * 16 + g;
#pragma unroll
        for (int nt = 0; nt < 8; nt++) {
            int col = nwarp * 64 + nt * 8 + tq * 2;
            float bb0 = b2[col], bb1 = b2[col + 1];
            unsigned xh = *(const unsigned*)(x1hi + (size_t)r0 * XST + col);
            unsigned xl = *(const unsigned*)(x1lo + (size_t)r0 * XST + col);
            float x0 = __uint_as_float(xh << 16) + __uint_as_float(xl << 16);
            float x1v = __uint_as_float(xh & 0xffff0000u) + __uint_as_float(xl & 0xffff0000u);
            *(float2*)(utmp + (size_t)r0 * VST + col) =
                make_float2(x0 + acc[mt][nt][0] + bb0, x1v + acc[mt][nt][1] + bb1);
            unsigned yh = *(const unsigned*)(x1hi + (size_t)(r0 + 8) * XST + col);
            unsigned yl = *(const unsigned*)(x1lo + (size_t)(r0 + 8) * XST + col);
            float y0 = __uint_as_float(yh << 16) + __uint_as_float(yl << 16);
            float y1 = __uint_as_float(yh & 0xffff0000u) + __uint_as_float(yl & 0xffff0000u);
            *(float2*)(utmp + (size_t)(r0 + 8) * VST + col) =
                make_float2(y0 + acc[mt][nt][2] + bb0, y1 + acc[mt][nt][3] + bb1);
        }
    }
    __syncthreads();

    // ---- final LN -> out_x ----
    {
        int r = tid >> 2, q = tid & 3;
        float s1 = 0.f;
#pragma unroll
        for (int i = 0; i < 16; i++) {
            int col = i * 16 + q * 4;
            float4 v = *(float4*)(utmp + (size_t)r * VST + col);
            s1 += v.x + v.y + v.z + v.w;
        }
        s1 += __shfl_xor_sync(0xffffffffu, s1, 1);
        s1 += __shfl_xor_sync(0xffffffffu, s1, 2);
        float mean = s1 * (1.f / 256.f);
        float s2 = 0.f;
#pragma unroll
        for (int i = 0; i < 16; i++) {
            int col = i * 16 + q * 4;
            float4 v = *(float4*)(utmp + (size_t)r * VST + col);
            float dx = v.x - mean, dy = v.y - mean, dz = v.z - mean, dw = v.w - mean;
            s2 += dx * dx + dy * dy + dz * dz + dw * dw;
        }
        s2 += __shfl_xor_sync(0xffffffffu, s2, 1);
        s2 += __shfl_xor_sync(0xffffffffu, s2, 2);
        float rstd = rsqrtf(s2 * (1.f / 256.f) + 1e-5f);
        float* orow = out_x + (size_t)(m0 + r) * 256;
#pragma unroll
        for (int i = 0; i < 16; i++) {
            int col = i * 16 + q * 4;
            float4 v = *(float4*)(utmp + (size_t)r * VST + col);
            float4 gg = *(const float4*)(g2 + col);
            float4 bb = *(const float4*)(be2 + col);
            float4 o4;
            o4.x = (v.x - mean) * rstd * gg.x + bb.x;
            o4.y = (v.y - mean) * rstd * gg.y + bb.y;
            o4.z = (v.z - mean) * rstd * gg.z + bb.z;
            o4.w = (v.w - mean) * rstd * gg.w + bb.w;
            *(float4*)(orow + col) = o4;
        }
    }
}

// ---------------- fused CLS readout tail ----------------------------------
__device__ __forceinline__ float blk_sum256(float v, float* red, int h, int lane) {
#pragma unroll
    for (int o = 16; o; o >>= 1) v += __shfl_xor_sync(0xffffffffu, v, o);
    if (lane == 0) red[h] = v;
    __syncthreads();
    float t = 0.f;
#pragma unroll
    for (int i = 0; i < 8; i++) t += red[i];
    __syncthreads();
    return t;
}

__global__ void __launch_bounds__(256)
cls_tail(const float* __restrict__ CLS, const float* __restrict__ rkv,
         const unsigned char* __restrict__ cmask,
         const float* __restrict__ ro_w1, const float* __restrict__ ro_b1,
         const float* __restrict__ ro_w2, const float* __restrict__ ro_b2,
         const float* __restrict__ rg1, const float* __restrict__ rbe1,
         const float* __restrict__ rg2, const float* __restrict__ rbe2,
         float* __restrict__ out_c) {
    int b = blockIdx.x, tid = threadIdx.x, h = tid >> 5, lane = tid & 31;
    __shared__ float sq[256], c1s[256], h1s[256], red[8];
    __shared__ float sp[8 * 160];

    float clsv = CLS[(size_t)b * 256 + tid];
    sq[tid] = clsv;
    __syncthreads();

    const float scale = 0.17677669529663687f;
    const float* sqh = sq + h * 32;
    float svals[5];
    float smax = -INFINITY;
#pragma unroll
    for (int j = 0; j < 5; j++) {
        int m = lane + j * 32;
        float s = -INFINITY;
        if (m < NT) {
            const float* kr = rkv + (size_t)(b * NT + m) * 512 + h * 32;
            float s0 = 0.f;
#pragma unroll
            for (int d = 0; d < 32; d++) s0 = fmaf(sqh[d], kr[d], s0);
            s = s0 * scale;
            if (cmask[(size_t)b * NT + m]) s = -INFINITY;
        }
        svals[j] = s;
        smax = fmaxf(smax, s);
    }
#pragma unroll
    for (int o = 16; o; o >>= 1)
        smax = fmaxf(smax, __shfl_xor_sync(0xffffffffu, smax, o));
    float ssum = 0.f;
#pragma unroll
    for (int j = 0; j < 5; j++) {
        float p = __expf(svals[j] - smax);
        ssum += p;
        sp[h * 160 + lane + j * 32] = p;
    }
#pragma unroll
    for (int o = 16; o; o >>= 1)
        ssum += __shfl_xor_sync(0xffffffffu, ssum, o);
    __syncwarp();
    float inv = 1.f / ssum;
    float acc = 0.f;
    for (int m = 0; m < NT; m++)
        acc = fmaf(sp[h * 160 + m],
                   rkv[(size_t)(b * NT + m) * 512 + 256 + h * 32 + lane], acc);
    float v = clsv + acc * inv;
    __syncthreads();

    float mean = blk_sum256(v, red, h, lane) * (1.f / 256.f);
    float d = v - mean;
    float var = blk_sum256(d * d, red, h, lane) * (1.f / 256.f);
    float c1 = d * rsqrtf(var + 1e-5f) * rg1[tid] + rbe1[tid];
    c1s[tid] = c1;
    __syncthreads();

    {
        float a2 = 0.f;
        const float4* wr = (const float4*)(ro_w1 + (size_t)tid * 256);
#pragma unroll 8
        for (int i = 0; i < 64; i++) {
            float4 w = wr[i];
            float4 cc = *(const float4*)(c1s + i * 4);
            a2 = fmaf(w.x, cc.x, fmaf(w.y, cc.y, fmaf(w.z, cc.z, fmaf(w.w, cc.w, a2))));
        }
        h1s[tid] = fmaxf(a2 + ro_b1[tid], 0.f);
    }
    __syncthreads();

    float u;
    {
        float a2 = 0.f;
        const float4* wr = (const float4*)(ro_w2 + (size_t)tid * 256);
#pragma unroll 8
        for (int i = 0; i < 64; i++) {
            float4 w = wr[i];
            float4 cc = *(const float4*)(h1s + i * 4);
            a2 = fmaf(w.x, cc.x, fmaf(w.y, cc.y, fmaf(w.z, cc.z, fmaf(w.w, cc.w, a2))));
        }
        u = c1 + a2 + ro_b2[tid];
    }
    float mean2 = blk_sum256(u, red, h, lane) * (1.f / 256.f);
    float d2 = u - mean2;
    float var2 = blk_sum256(d2 * d2, red, h, lane) * (1.f / 256.f);
    out_c[(size_t)b * 256 + tid] = d2 * rsqrtf(var2 + 1e-5f) * rg2[tid] + rbe2[tid];
}

// ---------------- launch --------------------------------------------------
extern "C" void kernel_launch(void* const* d_in, const int* in_sizes, int n_in,
                              void* d_out, int out_size) {
    const float* node_x   = (const float*)d_in[0];
    const float* edge_x   = (const float*)d_in[1];
    const float* CLS      = (const float*)d_in[2];
    const unsigned char* nmask = (const unsigned char*)d_in[3];
    const unsigned char* cmask = (const unsigned char*)d_in[4];
    const float* w_qkv    = (const float*)d_in[5];
    const float* b_qkv    = (const float*)d_in[6];
    const float* w_kve    = (const float*)d_in[7];
    const float* b_kve    = (const float*)d_in[8];
    const float* w1       = (const float*)d_in[9];
    const float* b1       = (const float*)d_in[10];
    const float* w2       = (const float*)d_in[11];
    const float* b2       = (const float*)d_in[12];
    const float* g1       = (const float*)d_in[13];
    const float* be1      = (const float*)d_in[14];
    const float* g2       = (const float*)d_in[15];
    const float* be2      = (const float*)d_in[16];
    const float* ro_w_kv  = (const float*)d_in[17];
    const float* ro_b_kv  = (const float*)d_in[18];
    const float* ro_w1    = (const float*)d_in[19];
    const float* ro_b1    = (const float*)d_in[20];
    const float* ro_w2    = (const float*)d_in[21];
    const float* ro_b2    = (const float*)d_in[22];
    const float* ro_g1    = (const float*)d_in[23];
    const float* ro_be1   = (const float*)d_in[24];
    const float* ro_g2    = (const float*)d_in[25];
    const float* ro_be2   = (const float*)d_in[26];

    float* out_x = (float*)d_out;
    float* out_c = out_x + (size_t)BB * NN * DD;

    float *p_qkv, *p_kve, *p_attn, *p_rkv;
    __nv_bfloat16 *whi, *wlo;
    cudaGetSymbolAddress((void**)&p_qkv,  g_qkv);
    cudaGetSymbolAddress((void**)&p_kve,  g_kve);
    cudaGetSymbolAddress((void**)&p_attn, g_attn);
    cudaGetSymbolAddress((void**)&p_rkv,  g_rkv);
    cudaGetSymbolAddress((void**)&whi,    g_whi);
    cudaGetSymbolAddress((void**)&wlo,    g_wlo);

    cudaFuncSetAttribute(gemm_mma<false, false, true >, cudaFuncAttributeMaxDynamicSharedMemorySize, GEMM_SMEM);
    cudaFuncSetAttribute(gemm_mma<false, true,  false>, cudaFuncAttributeMaxDynamicSharedMemorySize, GEMM_SMEM);
    cudaFuncSetAttribute(attn_flash, cudaFuncAttributeMaxDynamicSharedMemorySize, ATT2_SMEM);
    cudaFuncSetAttribute(ffn_fused, cudaFuncAttributeMaxDynamicSharedMemorySize, FFN_SMEM);

    // fused weight conversion
    conv_all<<<(W_CONV + 255) / 256, 256>>>(w_qkv, w_kve, w1, w2, ro_w_kv, whi, wlo);

    // projections: qkv + edge-kv in ONE dual-job launch (BM=64)
    gemm_mma<false, false, true><<<6 * 128 + 4 * 256, 256, GEMM_SMEM>>>(
        node_x, edge_x, whi + OFF_QKV, wlo + OFF_QKV, b_qkv, p_qkv, BB * NN, 768,
        whi + OFF_KVE, wlo + OFF_KVE, b_kve, p_kve, BB * EE, 512,
        6 * 128, 6, 4);

    // flash attention
    attn_flash<<<dim3(HH, BB), 256, ATT2_SMEM>>>(p_qkv, p_kve, nmask, p_attn);

    // fused FFN block (256 threads, Round-11 proven): LN + FFN + res + LN
    ffn_fused<<<BB * NN / 64, 256, FFN_SMEM>>>(
        node_x, p_attn,
        whi + OFF_W1, wlo + OFF_W1, whi + OFF_W2, wlo + OFF_W2,
        b1, b2, g1, be1, g2, be2, out_x);

    // readout: rkv = [CLS; x] @ ro_w_kv (CONCAT rows)
    gemm_mma<false, true, false><<<dim3(4, 129), 256, GEMM_SMEM>>>(
        out_x, CLS, whi + OFF_ROKV, wlo + OFF_ROKV, ro_b_kv, p_rkv, BB * NT, 512,
        nullptr, nullptr, nullptr, nullptr, 0, 0, 0, 0, 0);

    // fused CLS tail
    cls_tail<<<BB, 256>>>(CLS, p_rkv, cmask, ro_w1, ro_b1, ro_w2, ro_b2,
                          ro_g1, ro_be1, ro_g2, ro_be2, out_c);
}

// round 15
// speedup vs baseline: 1.0606x; 1.0144x over previous
#include <cuda_runtime.h>
#include <cuda_bf16.h>
#include <math.h>

// Shapes
#define BB   64
#define NN   128
#define EE   256
#define DD   256
#define HH   8
#define MT   384   // N + E
#define NT   129   // N + 1

// ---------------- scratch (device globals; no allocation) ----------------
__device__ float g_qkv [BB*NN*3*DD];
__device__ float g_kve [BB*EE*2*DD];
__device__ float g_attn[BB*NN*DD];
__device__ float g_rkv [BB*NT*2*DD];

// bf16 hi/lo weight buffers, layout [Nc][256] (k contiguous)
#define OFF_QKV   0
#define OFF_KVE   (OFF_QKV + 768*256)
#define OFF_W1    (OFF_KVE + 512*256)
#define OFF_W2    (OFF_W1  + 256*256)
#define OFF_ROKV  (OFF_W2  + 256*256)
#define W_CONV    (OFF_ROKV+ 512*256)
__device__ __nv_bfloat16 g_whi[W_CONV];
__device__ __nv_bfloat16 g_wlo[W_CONV];

// ---------------- fused weight conversion (one launch) -------------------
__global__ void conv_all(const float* __restrict__ w_qkv,
                         const float* __restrict__ w_kve,
                         const float* __restrict__ w1,
                         const float* __restrict__ w2,
                         const float* __restrict__ ro_w_kv,
                         __nv_bfloat16* __restrict__ hi,
                         __nv_bfloat16* __restrict__ lo) {
    int i = blockIdx.x * 256 + threadIdx.x;
    if (i >= W_CONV) return;
    const float* W; int Nc; bool direct; int off;
    if      (i < OFF_KVE ) { W = w_qkv;   Nc = 768; direct = false; off = OFF_QKV;  }
    else if (i < OFF_W1  ) { W = w_kve;   Nc = 512; direct = false; off = OFF_KVE;  }
    else if (i < OFF_W2  ) { W = w1;      Nc = 256; direct = true;  off = OFF_W1;   }
    else if (i < OFF_ROKV) { W = w2;      Nc = 256; direct = true;  off = OFF_W2;   }
    else                   { W = ro_w_kv; Nc = 512; direct = false; off = OFF_ROKV; }
    int li = i - off;
    int n = li >> 8, k = li & 255;
    float v = direct ? W[(size_t)n * 256 + k] : W[(size_t)k * Nc + n];
    __nv_bfloat16 h = __float2bfloat16(v);
    hi[i] = h;
    lo[i] = __float2bfloat16(v - __bfloat162float(h));
}

// ---------------- mma / ldmatrix / cp.async helpers -----------------------
__device__ __forceinline__ void mma_bf16(float* c, const unsigned* a, const unsigned* b) {
    asm volatile(
        "mma.sync.aligned.m16n8k16.row.col.f32.bf16.bf16.f32 "
        "{%0,%1,%2,%3}, {%4,%5,%6,%7}, {%8,%9}, {%0,%1,%2,%3};\n"
        : "+f"(c[0]), "+f"(c[1]), "+f"(c[2]), "+f"(c[3])
        : "r"(a[0]), "r"(a[1]), "r"(a[2]), "r"(a[3]), "r"(b[0]), "r"(b[1]));
}

__device__ __forceinline__ void ldsm4(unsigned* r, const void* p) {
    unsigned a = (unsigned)__cvta_generic_to_shared(p);
    asm volatile("ldmatrix.sync.aligned.m8n8.x4.shared.b16 {%0,%1,%2,%3}, [%4];"
                 : "=r"(r[0]), "=r"(r[1]), "=r"(r[2]), "=r"(r[3]) : "r"(a));
}

__device__ __forceinline__ void cpa16(void* s, const void* g) {
    unsigned a = (unsigned)__cvta_generic_to_shared(s);
    asm volatile("cp.async.cg.shared.global [%0], [%1], 16;" :: "r"(a), "l"(g));
}
#define CP_COMMIT() asm volatile("cp.async.commit_group;" ::: "memory")
#define CP_WAIT0()  asm volatile("cp.async.wait_group 0;" ::: "memory")

// packed-cvt hi/lo split: low half = x, high half = y
__device__ __forceinline__ void split2(float x, float y, unsigned& hi, unsigned& lo) {
    unsigned h;
    asm("cvt.rn.bf16x2.f32 %0, %1, %2;" : "=r"(h) : "f"(y), "f"(x));
    float fx = __uint_as_float(h << 16);
    float fy = __uint_as_float(h & 0xffff0000u);
    unsigned l;
    asm("cvt.rn.bf16x2.f32 %0, %1, %2;" : "=r"(l) : "f"(y - fy), "f"(x - fx));
    hi = h; lo = l;
}

__device__ __forceinline__ unsigned pack_bf16(float x, float y) {
    unsigned h;
    asm("cvt.rn.bf16x2.f32 %0, %1, %2;" : "=r"(h) : "f"(y), "f"(x));
    return h;
}

#define GST 72   // smem row stride in bf16 (144B)
#define GEMM_SMEM ((2*64*GST + 4*128*GST) * (int)sizeof(__nv_bfloat16))   // 92160

// ---------------- bf16-split tensor-core GEMM (BM=64, pipelined) ----------
// nskip: n-blocks with bx < nskip drop the ah*bl pass (score-path columns)
template<bool RELU, bool CONCAT, bool DUAL>
__global__ void __launch_bounds__(256)
gemm_mma(const float* __restrict__ A, const float* __restrict__ A2,
         const __nv_bfloat16* __restrict__ Whi,
         const __nv_bfloat16* __restrict__ Wlo,
         const float* __restrict__ bias,
         float* __restrict__ C, int M, int Nc,
         const __nv_bfloat16* Whi2, const __nv_bfloat16* Wlo2,
         const float* bias2, float* C2, int M2, int Nc2,
         int nb0, int gx0, int gx1, int nskip0, int nskip1) {
    extern __shared__ __nv_bfloat16 sm[];
    __nv_bfloat16* sAhi = sm;
    __nv_bfloat16* sAlo = sAhi + 64 * GST;
    __nv_bfloat16* sBhi = sAlo + 64 * GST;
    __nv_bfloat16* sBlo = sBhi + 2 * 128 * GST;

    int bx, by;
    const float* Ap = A;
    const __nv_bfloat16* Whip = Whi;
    const __nv_bfloat16* Wlop = Wlo;
    const float* biasp = bias;
    float* Cp = C;
    int Mp = M, Ncp = Nc, nskip = nskip0;
    if (DUAL) {
        int bid = blockIdx.x;
        if (bid < nb0) { bx = bid % gx0; by = bid / gx0; }
        else {
            bid -= nb0; bx = bid % gx1; by = bid / gx1;
            Ap = A2; Whip = Whi2; Wlop = Wlo2; biasp = bias2; Cp = C2;
            Mp = M2; Ncp = Nc2; nskip = nskip1;
        }
    } else {
        bx = blockIdx.x; by = blockIdx.y;
    }
    bool uselo = bx >= nskip;

    int tid = threadIdx.x;
    int lane = tid & 31, warp = tid >> 5;
    int g = lane >> 2, tq = lane & 3;
    int mbase = (warp >> 2) * 32;
    int nbase = (warp & 3) * 32;
    int m0 = by * 64;
    int n0 = bx * 128;

    int lr = lane & 7, sel = lane >> 3;
    const __nv_bfloat16* aHiB = sAhi + (size_t)(mbase + (sel & 1) * 8 + lr) * GST + ((sel >> 1) & 1) * 8;
    const __nv_bfloat16* aLoB = sAlo + (size_t)(mbase + (sel & 1) * 8 + lr) * GST + ((sel >> 1) & 1) * 8;
    size_t bOff = (size_t)(nbase + (sel >> 1) * 8 + lr) * GST + (sel & 1) * 8;

    int ar = tid >> 2, aq = tid & 3;
    int arr = m0 + ar;
    bool avalid = arr < Mp;
    const float* aRow;
    if (CONCAT) {
        int bidx = arr / NT, t = arr - bidx * NT;
        aRow = (t == 0) ? A2 + (size_t)bidx * 256
                        : Ap + (size_t)(bidx * NN + t - 1) * 256;
    } else {
        aRow = Ap + (size_t)arr * 256;
    }
    int colb = aq * 16;
    aRow += colb;

    int bn = tid >> 1, bck = (tid & 1) * 32;

    float acc[2][4][4];
#pragma unroll
    for (int mt = 0; mt < 2; mt++)
#pragma unroll
        for (int nt = 0; nt < 4; nt++)
#pragma unroll
            for (int i = 0; i < 4; i++) acc[mt][nt][i] = 0.f;

    float4 av[4];
    {
        const __nv_bfloat16* wh = Whip + (size_t)(n0 + bn) * 256 + bck;
        const __nv_bfloat16* wl = Wlop + (size_t)(n0 + bn) * 256 + bck;
        __nv_bfloat16* dh = sBhi + (size_t)bn * GST + bck;
        __nv_bfloat16* dl = sBlo + (size_t)bn * GST + bck;
#pragma unroll
        for (int i = 0; i < 4; i++) {
            cpa16(dh + i * 8, wh + i * 8);
            cpa16(dl + i * 8, wl + i * 8);
        }
        CP_COMMIT();
#pragma unroll
        for (int i = 0; i < 4; i++)
            av[i] = avalid ? *(const float4*)(aRow + i * 4)
                           : make_float4(0.f, 0.f, 0.f, 0.f);
#pragma unroll
        for (int i = 0; i < 4; i++) {
            unsigned h01, l01, h23, l23;
            split2(av[i].x, av[i].y, h01, l01);
            split2(av[i].z, av[i].w, h23, l23);
            int c = colb + i * 4;
            *(unsigned*)(sAhi + (size_t)ar * GST + c)     = h01;
            *(unsigned*)(sAhi + (size_t)ar * GST + c + 2) = h23;
            *(unsigned*)(sAlo + (size_t)ar * GST + c)     = l01;
            *(unsigned*)(sAlo + (size_t)ar * GST + c + 2) = l23;
        }
        CP_WAIT0();
        __syncthreads();
    }

    for (int it = 0; it < 4; it++) {
        int nk = it + 1;
        if (nk < 4) {
            int buf = nk & 1;
            const __nv_bfloat16* wh = Whip + (size_t)(n0 + bn) * 256 + nk * 64 + bck;
            const __nv_bfloat16* wl = Wlop + (size_t)(n0 + bn) * 256 + nk * 64 + bck;
            __nv_bfloat16* dh = sBhi + (size_t)buf * 128 * GST + (size_t)bn * GST + bck;
            __nv_bfloat16* dl = sBlo + (size_t)buf * 128 * GST + (size_t)bn * GST + bck;
#pragma unroll
            for (int i = 0; i < 4; i++) {
                cpa16(dh + i * 8, wh + i * 8);
                cpa16(dl + i * 8, wl + i * 8);
            }
            CP_COMMIT();
#pragma unroll
            for (int i = 0; i < 4; i++)
                av[i] = avalid ? *(const float4*)(aRow + nk * 64 + i * 4)
                               : make_float4(0.f, 0.f, 0.f, 0.f);
        }

        {
            size_t bufo = (size_t)(it & 1) * 128 * GST;
            const __nv_bfloat16* bHiB = sBhi + bufo + bOff;
            const __nv_bfloat16* bLoB = sBlo + bufo + bOff;
#pragma unroll
            for (int kk = 0; kk < 64; kk += 16) {
                unsigned ah[2][4], al[2][4], bh[4][2], bl[4][2];
#pragma unroll
                for (int mt = 0; mt < 2; mt++) {
                    ldsm4(ah[mt], aHiB + (size_t)mt * 16 * GST + kk);
                    ldsm4(al[mt], aLoB + (size_t)mt * 16 * GST + kk);
                }
#pragma unroll
                for (int p = 0; p < 2; p++) {
                    unsigned t[4];
                    ldsm4(t, bHiB + (size_t)p * 16 * GST + kk);
                    bh[2*p][0] = t[0]; bh[2*p][1] = t[1];
                    bh[2*p+1][0] = t[2]; bh[2*p+1][1] = t[3];
                    ldsm4(t, bLoB + (size_t)p * 16 * GST + kk);
                    bl[2*p][0] = t[0]; bl[2*p][1] = t[1];
                    bl[2*p+1][0] = t[2]; bl[2*p+1][1] = t[3];
                }
#pragma unroll
                for (int mt = 0; mt < 2; mt++)
#pragma unroll
                    for (int nt = 0; nt < 4; nt++) {
                        mma_bf16(acc[mt][nt], ah[mt], bh[nt]);
                        mma_bf16(acc[mt][nt], al[mt], bh[nt]);
                        if (uselo) mma_bf16(acc[mt][nt], ah[mt], bl[nt]);
                    }
            }
        }
        __syncthreads();
        if (nk < 4) {
#pragma unroll
            for (int i = 0; i < 4; i++) {
                unsigned h01, l01, h23, l23;
                split2(av[i].x, av[i].y, h01, l01);
                split2(av[i].z, av[i].w, h23, l23);
                int c = colb + i * 4;
                *(unsigned*)(sAhi + (size_t)ar * GST + c)     = h01;
                *(unsigned*)(sAhi + (size_t)ar * GST + c + 2) = h23;
                *(unsigned*)(sAlo + (size_t)ar * GST + c)     = l01;
                *(unsigned*)(sAlo + (size_t)ar * GST + c + 2) = l23;
            }
            CP_WAIT0();
            __syncthreads();
        }
    }

#pragma unroll
    for (int mt = 0; mt < 2; mt++) {
        int r0 = m0 + mbase + mt * 16 + g;
#pragma unroll
        for (int nt = 0; nt < 4; nt++) {
            int col = n0 + nbase + nt * 8 + tq * 2;
            float b0 = biasp[col], b1 = biasp[col + 1];
            if (r0 < Mp) {
                float v0 = acc[mt][nt][0] + b0;
                float v1 = acc[mt][nt][1] + b1;
                if (RELU) { v0 = fmaxf(v0, 0.f); v1 = fmaxf(v1, 0.f); }
                Cp[(size_t)r0 * Ncp + col]     = v0;
                Cp[(size_t)r0 * Ncp + col + 1] = v1;
            }
            if (r0 + 8 < Mp) {
                float v2 = acc[mt][nt][2] + b0;
                float v3 = acc[mt][nt][3] + b1;
                if (RELU) { v2 = fmaxf(v2, 0.f); v3 = fmaxf(v3, 0.f); }
                Cp[(size_t)(r0 + 8) * Ncp + col]     = v2;
                Cp[(size_t)(r0 + 8) * Ncp + col + 1] = v3;
            }
        }
    }
}

// ---------------- flash attention on tensor cores -------------------------
// S: single-pass q_hi @ K_hi (score abs err ~3e-5, inside budget).
// P@V: full 3-pass hi/lo (precision-critical).
#define AK_STR 40
#define AV_STR 392
#define ATT2_SMEM ((384*AK_STR + 2*32*AV_STR) * (int)sizeof(__nv_bfloat16))

__global__ void __launch_bounds__(256, 2)
attn_flash(const float* __restrict__ qkv,
           const float* __restrict__ kve,
           const unsigned char* __restrict__ nmask,
           float* __restrict__ out) {
    int h = blockIdx.x, b = blockIdx.y;
    extern __shared__ __nv_bfloat16 smb[];
    __nv_bfloat16* Khi  = smb;
    __nv_bfloat16* Vthi = Khi  + 384 * AK_STR;
    __nv_bfloat16* Vtlo = Vthi + 32 * AV_STR;

    int tid = threadIdx.x;
    for (int idx = tid; idx < MT * 8; idx += 256) {
        int m = idx >> 3, d4 = (idx & 7) * 4;
        float4 kv4, vv4;
        if (m < NN) {
            const float* base = qkv + (size_t)(b * NN + m) * 768 + h * 32 + d4;
            kv4 = *(const float4*)(base + 256);
            vv4 = *(const float4*)(base + 512);
        } else {
            const float* base = kve + (size_t)(b * EE + (m - NN)) * 512 + h * 32 + d4;
            kv4 = *(const float4*)(base);
            vv4 = *(const float4*)(base + 256);
        }
        *(unsigned*)(Khi + m * AK_STR + d4)     = pack_bf16(kv4.x, kv4.y);
        *(unsigned*)(Khi + m * AK_STR + d4 + 2) = pack_bf16(kv4.z, kv4.w);
        float vs[4] = { vv4.x, vv4.y, vv4.z, vv4.w };
#pragma unroll
        for (int j = 0; j < 4; j++) {
            __nv_bfloat16 vh = __float2bfloat16(vs[j]);
            Vthi[(d4 + j) * AV_STR + m] = vh;
            Vtlo[(d4 + j) * AV_STR + m] = __float2bfloat16(vs[j] - __bfloat162float(vh));
        }
    }
    __syncthreads();

    int lane = tid & 31, warp = tid >> 5;
    int g = lane >> 2, tq = lane & 3;
    int lr = lane & 7, sel = lane >> 3;
    int r0 = warp * 16 + g;
    int r1 = r0 + 8;
    const float scale = 0.17677669529663687f;

    const __nv_bfloat16* kHiB = Khi  + (size_t)((sel >> 1) * 8 + lr) * AK_STR + (sel & 1) * 8;
    const __nv_bfloat16* vHiB = Vthi + (size_t)((sel >> 1) * 8 + lr) * AV_STR + (sel & 1) * 8;
    const __nv_bfloat16* vLoB = Vtlo + (size_t)((sel >> 1) * 8 + lr) * AV_STR + (sel & 1) * 8;

    // Q fragments: hi only, scale folded
    unsigned qh[2][4];
    {
        const float* q0p = qkv + (size_t)(b * NN + r0) * 768 + h * 32;
        const float* q1p = qkv + (size_t)(b * NN + r1) * 768 + h * 32;
#pragma unroll
        for (int kk2 = 0; kk2 < 2; kk2++) {
            int kb = kk2 * 16 + tq * 2;
            float2 v;
            v = *(const float2*)(q0p + kb);
            qh[kk2][0] = pack_bf16(v.x * scale, v.y * scale);
            v = *(const float2*)(q1p + kb);
            qh[kk2][1] = pack_bf16(v.x * scale, v.y * scale);
            v = *(const float2*)(q0p + kb + 8);
            qh[kk2][2] = pack_bf16(v.x * scale, v.y * scale);
            v = *(const float2*)(q1p + kb + 8);
            qh[kk2][3] = pack_bf16(v.x * scale, v.y * scale);
        }
    }

    const unsigned short* mrow0 =
        (const unsigned short*)(nmask + (size_t)(b * NN + r0) * MT);
    const unsigned short* mrow1 =
        (const unsigned short*)(nmask + (size_t)(b * NN + r1) * MT);

    float m0 = -INFINITY, m1 = -INFINITY, l0 = 0.f, l1 = 0.f;
    float o[4][4];
#pragma unroll
    for (int nt = 0; nt < 4; nt++)
#pragma unroll
        for (int i = 0; i < 4; i++) o[nt][i] = 0.f;

#pragma unroll
    for (int c = 0; c < 6; c++) {
        int tkb = c * 64;
        float s[8][4];
#pragma unroll
        for (int nt = 0; nt < 8; nt++)
#pragma unroll
            for (int i = 0; i < 4; i++) s[nt][i] = 0.f;

        // S = q_hi @ K_hi (single pass)
#pragma unroll
        for (int kk2 = 0; kk2 < 2; kk2++) {
#pragma unroll
            for (int p = 0; p < 4; p++) {
                unsigned t[4];
                ldsm4(t, kHiB + (size_t)(tkb + p * 16) * AK_STR + kk2 * 16);
                unsigned bhA[2] = { t[0], t[1] }, bhB[2] = { t[2], t[3] };
                mma_bf16(s[2*p],   qh[kk2], bhA);
                mma_bf16(s[2*p+1], qh[kk2], bhB);
            }
        }

        float cm0 = -INFINITY, cm1 = -INFINITY;
#pragma unroll
        for (int nt = 0; nt < 8; nt++) {
            int t = tkb + nt * 8 + tq * 2;
            unsigned short mm0 = mrow0[t >> 1];
            unsigned short mm1 = mrow1[t >> 1];
            if (mm0 & 0x00FFu) s[nt][0] = -INFINITY;
            if (mm0 & 0xFF00u) s[nt][1] = -INFINITY;
            if (mm1 & 0x00FFu) s[nt][2] = -INFINITY;
            if (mm1 & 0xFF00u) s[nt][3] = -INFINITY;
            cm0 = fmaxf(cm0, fmaxf(s[nt][0], s[nt][1]));
            cm1 = fmaxf(cm1, fmaxf(s[nt][2], s[nt][3]));
        }
        cm0 = fmaxf(cm0, __shfl_xor_sync(0xffffffffu, cm0, 1));
        cm0 = fmaxf(cm0, __shfl_xor_sync(0xffffffffu, cm0, 2));
        cm1 = fmaxf(cm1, __shfl_xor_sync(0xffffffffu, cm1, 1));
        cm1 = fmaxf(cm1, __shfl_xor_sync(0xffffffffu, cm1, 2));

        float nm0 = fmaxf(m0, cm0), nm1 = fmaxf(m1, cm1);
        float corr0 = (m0 == -INFINITY) ? 0.f : __expf(m0 - nm0);
        float corr1 = (m1 == -INFINITY) ? 0.f : __expf(m1 - nm1);
        float e0 = (nm0 == -INFINITY) ? 0.f : nm0;
        float e1 = (nm1 == -INFINITY) ? 0.f : nm1;
        m0 = nm0; m1 = nm1;
        l0 *= corr0; l1 *= corr1;
#pragma unroll
        for (int nt = 0; nt < 4; nt++) {
            o[nt][0] *= corr0; o[nt][1] *= corr0;
            o[nt][2] *= corr1; o[nt][3] *= corr1;
        }

#pragma unroll
        for (int ks = 0; ks < 4; ks++) {
            float p00 = __expf(s[2*ks][0]   - e0);
            float p01 = __expf(s[2*ks][1]   - e0);
            float p02 = __expf(s[2*ks][2]   - e1);
            float p03 = __expf(s[2*ks][3]   - e1);
            float p10 = __expf(s[2*ks+1][0] - e0);
            float p11 = __expf(s[2*ks+1][1] - e0);
            float p12 = __expf(s[2*ks+1][2] - e1);
            float p13 = __expf(s[2*ks+1][3] - e1);
            l0 += p00 + p01 + p10 + p11;
            l1 += p02 + p03 + p12 + p13;
            unsigned ah[4], al[4];
            split2(p00, p01, ah[0], al[0]);
            split2(p02, p03, ah[1], al[1]);
            split2(p10, p11, ah[2], al[2]);
            split2(p12, p13, ah[3], al[3]);
#pragma unroll
            for (int p = 0; p < 2; p++) {
                unsigned t[4], u[4];
                ldsm4(t, vHiB + (size_t)p * 16 * AV_STR + tkb + ks * 16);
                ldsm4(u, vLoB + (size_t)p * 16 * AV_STR + tkb + ks * 16);
                unsigned bhA[2] = { t[0], t[1] }, bhB[2] = { t[2], t[3] };
                unsigned blA[2] = { u[0], u[1] }, blB[2] = { u[2], u[3] };
                mma_bf16(o[2*p],   ah, bhA);
                mma_bf16(o[2*p],   al, bhA);
                mma_bf16(o[2*p],   ah, blA);
                mma_bf16(o[2*p+1], ah, bhB);
                mma_bf16(o[2*p+1], al, bhB);
                mma_bf16(o[2*p+1], ah, blB);
            }
        }
    }

    l0 += __shfl_xor_sync(0xffffffffu, l0, 1);
    l0 += __shfl_xor_sync(0xffffffffu, l0, 2);
    l1 += __shfl_xor_sync(0xffffffffu, l1, 1);
    l1 += __shfl_xor_sync(0xffffffffu, l1, 2);
    float inv0 = 1.f / l0, inv1 = 1.f / l1;
    size_t ob0 = (size_t)(b * NN + r0) * DD + h * 32;
    size_t ob1 = (size_t)(b * NN + r1) * DD + h * 32;
#pragma unroll
    for (int nt = 0; nt < 4; nt++) {
        int dcol = nt * 8 + tq * 2;
        *(float2*)(out + ob0 + dcol) = make_float2(o[nt][0] * inv0, o[nt][1] * inv0);
        *(float2*)(out + ob1 + dcol) = make_float2(o[nt][2] * inv1, o[nt][3] * inv1);
    }
}

// ---------------- fused FFN megakernel (256 threads — proven) -------------
#define XST 264
#define WST 40
#define VST 260
#define FFN_SMEM ((4*64*XST + 2*2*256*WST) * (int)sizeof(__nv_bfloat16))  // 217088

__global__ void __launch_bounds__(256)
ffn_fused(const float* __restrict__ nx, const float* __restrict__ at,
          const __nv_bfloat16* __restrict__ w1hi, const __nv_bfloat16* __restrict__ w1lo,
          const __nv_bfloat16* __restrict__ w2hi, const __nv_bfloat16* __restrict__ w2lo,
          const float* __restrict__ b1, const float* __restrict__ b2,
          const float* __restrict__ g1, const float* __restrict__ be1,
          const float* __restrict__ g2, const float* __restrict__ be2,
          float* __restrict__ out_x) {
    extern __shared__ __nv_bfloat16 sm[];
    __nv_bfloat16* x1hi = sm;
    __nv_bfloat16* x1lo = x1hi + 64 * XST;
    __nv_bfloat16* h1hi = x1lo + 64 * XST;
    __nv_bfloat16* h1lo = h1hi + 64 * XST;
    __nv_bfloat16* sW   = h1lo + 64 * XST;
    float* vtmp = (float*)h1hi;
    float* utmp = (float*)sW;

    int tid = threadIdx.x;
    int lane = tid & 31, warp = tid >> 5;
    int g = lane >> 2, tq = lane & 3;
    int lr = lane & 7, sel = lane >> 3;
    int mbase = (warp >> 2) * 32;
    int nwarp = warp & 3;
    int m0 = blockIdx.x * 64;

    {
        const __nv_bfloat16* wh = w1hi + (size_t)tid * 256;
        const __nv_bfloat16* wl = w1lo + (size_t)tid * 256;
        __nv_bfloat16* dh = sW + (size_t)tid * WST;
        __nv_bfloat16* dl = sW + 256 * WST + (size_t)tid * WST;
#pragma unroll
        for (int i = 0; i < 4; i++) { cpa16(dh + i * 8, wh + i * 8); cpa16(dl + i * 8, wl + i * 8); }
        CP_COMMIT();
    }

    {
        int r = tid >> 2, q = tid & 3;
        const float* nrow = nx + (size_t)(m0 + r) * 256;
        const float* arow = at + (size_t)(m0 + r) * 256;
        float s1 = 0.f;
#pragma unroll
        for (int i = 0; i < 16; i++) {
            int col = i * 16 + q * 4;
            float4 v = *(const float4*)(nrow + col);
            float4 a = *(const float4*)(arow + col);
            v.x += a.x; v.y += a.y; v.z += a.z; v.w += a.w;
            *(float4*)(vtmp + (size_t)r * VST + col) = v;
            s1 += v.x + v.y + v.z + v.w;
        }
        s1 += __shfl_xor_sync(0xffffffffu, s1, 1);
        s1 += __shfl_xor_sync(0xffffffffu, s1, 2);
        float mean = s1 * (1.f / 256.f);
        float s2 = 0.f;
#pragma unroll
        for (int i = 0; i < 16; i++) {
            int col = i * 16 + q * 4;
            float4 v = *(float4*)(vtmp + (size_t)r * VST + col);
            v.x -= mean; v.y -= mean; v.z -= mean; v.w -= mean;
            *(float4*)(vtmp + (size_t)r * VST + col) = v;
            s2 += v.x * v.x + v.y * v.y + v.z * v.z + v.w * v.w;
        }
        s2 += __shfl_xor_sync(0xffffffffu, s2, 1);
        s2 += __shfl_xor_sync(0xffffffffu, s2, 2);
        float rstd = rsqrtf(s2 * (1.f / 256.f) + 1e-5f);
#pragma unroll
        for (int i = 0; i < 16; i++) {
            int col = i * 16 + q * 4;
            float4 v = *(float4*)(vtmp + (size_t)r * VST + col);
            float4 gg = *(const float4*)(g1 + col);
            float4 bb = *(const float4*)(be1 + col);
            float x0 = v.x * rstd * gg.x + bb.x;
            float x1 = v.y * rstd * gg.y + bb.y;
            float x2 = v.z * rstd * gg.z + bb.z;
            float x3 = v.w * rstd * gg.w + bb.w;
            unsigned h01, l01, h23, l23;
            split2(x0, x1, h01, l01);
            split2(x2, x3, h23, l23);
            *(unsigned*)(x1hi + (size_t)r * XST + col)     = h01;
            *(unsigned*)(x1hi + (size_t)r * XST + col + 2) = h23;
            *(unsigned*)(x1lo + (size_t)r * XST + col)     = l01;
            *(unsigned*)(x1lo + (size_t)r * XST + col + 2) = l23;
        }
    }
    CP_WAIT0();
    __syncthreads();

    const __nv_bfloat16* a1HiB = x1hi + (size_t)(mbase + (sel & 1) * 8 + lr) * XST + ((sel >> 1) & 1) * 8;
    const __nv_bfloat16* a1LoB = x1lo + (size_t)(mbase + (sel & 1) * 8 + lr) * XST + ((sel >> 1) & 1) * 8;
    const __nv_bfloat16* a2HiB = h1hi + (size_t)(mbase + (sel & 1) * 8 + lr) * XST + ((sel >> 1) & 1) * 8;
    const __nv_bfloat16* a2LoB = h1lo + (size_t)(mbase + (sel & 1) * 8 + lr) * XST + ((sel >> 1) & 1) * 8;
    size_t bOff = (size_t)(nwarp * 64 + (sel >> 1) * 8 + lr) * WST + (sel & 1) * 8;

    float acc[2][8][4];
#pragma unroll
    for (int mt = 0; mt < 2; mt++)
#pragma unroll
        for (int nt = 0; nt < 8; nt++)
#pragma unroll
            for (int i = 0; i < 4; i++) acc[mt][nt][i] = 0.f;

#pragma unroll
    for (int ck = 0; ck < 8; ck++) {
        if (ck < 7) {
            int buf = (ck + 1) & 1;
            const __nv_bfloat16* wh = w1hi + (size_t)tid * 256 + (ck + 1) * 32;
            const __nv_bfloat16* wl = w1lo + (size_t)tid * 256 + (ck + 1) * 32;
            __nv_bfloat16* dh = sW + (size_t)buf * 2 * 256 * WST + (size_t)tid * WST;
            __nv_bfloat16* dl = dh + 256 * WST;
#pragma unroll
            for (int i = 0; i < 4; i++) { cpa16(dh + i * 8, wh + i * 8); cpa16(dl + i * 8, wl + i * 8); }
            CP_COMMIT();
        }
        size_t bufo = (size_t)(ck & 1) * 2 * 256 * WST;
#pragma unroll
        for (int kk = 0; kk < 32; kk += 16) {
            unsigned ah[2][4], al[2][4];
#pragma unroll
            for (int mt = 0; mt < 2; mt++) {
                ldsm4(ah[mt], a1HiB + (size_t)mt * 16 * XST + ck * 32 + kk);
                ldsm4(al[mt], a1LoB + (size_t)mt * 16 * XST + ck * 32 + kk);
            }
#pragma unroll
            for (int p = 0; p < 4; p++) {
                unsigned t[4], u[4];
                ldsm4(t, sW + bufo + bOff + (size_t)p * 16 * WST + kk);
                ldsm4(u, sW + bufo + 256 * WST + bOff + (size_t)p * 16 * WST + kk);
                unsigned bhA[2] = { t[0], t[1] }, bhB[2] = { t[2], t[3] };
                unsigned blA[2] = { u[0], u[1] }, blB[2] = { u[2], u[3] };
#pragma unroll
                for (int mt = 0; mt < 2; mt++) {
                    mma_bf16(acc[mt][2*p],   ah[mt], bhA);
                    mma_bf16(acc[mt][2*p],   al[mt], bhA);
                    mma_bf16(acc[mt][2*p],   ah[mt], blA);
                    mma_bf16(acc[mt][2*p+1], ah[mt], bhB);
                    mma_bf16(acc[mt][2*p+1], al[mt], bhB);
                    mma_bf16(acc[mt][2*p+1], ah[mt], blB);
                }
            }
        }
        if (ck < 7) { CP_WAIT0(); }
        __syncthreads();
    }

    {
        const __nv_bfloat16* wh = w2hi + (size_t)tid * 256;
        const __nv_bfloat16* wl = w2lo + (size_t)tid * 256;
        __nv_bfloat16* dh = sW + (size_t)tid * WST;
        __nv_bfloat16* dl = sW + 256 * WST + (size_t)tid * WST;
#pragma unroll
        for (int i = 0; i < 4; i++) { cpa16(dh + i * 8, wh + i * 8); cpa16(dl + i * 8, wl + i * 8); }
        CP_COMMIT();
    }

#pragma unroll
    for (int mt = 0; mt < 2; mt++) {
        int r0 = mbase + mt * 16 + g;
#pragma unroll
        for (int nt = 0; nt < 8; nt++) {
            int col = nwarp * 64 + nt * 8 + tq * 2;
            float bb0 = b1[col], bb1 = b1[col + 1];
            float v0 = fmaxf(acc[mt][nt][0] + bb0, 0.f);
            float v1 = fmaxf(acc[mt][nt][1] + bb1, 0.f);
            float v2 = fmaxf(acc[mt][nt][2] + bb0, 0.f);
            float v3 = fmaxf(acc[mt][nt][3] + bb1, 0.f);
            unsigned h01, l01, h23, l23;
            split2(v0, v1, h01, l01);
            split2(v2, v3, h23, l23);
            *(unsigned*)(h1hi + (size_t)r0 * XST + col)       = h01;
            *(unsigned*)(h1lo + (size_t)r0 * XST + col)       = l01;
            *(unsigned*)(h1hi + (size_t)(r0 + 8) * XST + col) = h23;
            *(unsigned*)(h1lo + (size_t)(r0 + 8) * XST + col) = l23;
            acc[mt][nt][0] = 0.f; acc[mt][nt][1] = 0.f;
            acc[mt][nt][2] = 0.f; acc[mt][nt][3] = 0.f;
        }
    }
    CP_WAIT0();
    __syncthreads();

#pragma unroll
    for (int ck = 0; ck < 8; ck++) {
        if (ck < 7) {
            int buf = (ck + 1) & 1;
            const __nv_bfloat16* wh = w2hi + (size_t)tid * 256 + (ck + 1) * 32;
            const __nv_bfloat16* wl = w2lo + (size_t)tid * 256 + (ck + 1) * 32;
            __nv_bfloat16* dh = sW + (size_t)buf * 2 * 256 * WST + (size_t)tid * WST;
            __nv_bfloat16* dl = dh + 256 * WST;
#pragma unroll
            for (int i = 0; i < 4; i++) { cpa16(dh + i * 8, wh + i * 8); cpa16(dl + i * 8, wl + i * 8); }
            CP_COMMIT();
        }
        size_t bufo = (size_t)(ck & 1) * 2 * 256 * WST;
#pragma unroll
        for (int kk = 0; kk < 32; kk += 16) {
            unsigned ah[2][4], al[2][4];
#pragma unroll
            for (int mt = 0; mt < 2; mt++) {
                ldsm4(ah[mt], a2HiB + (size_t)mt * 16 * XST + ck * 32 + kk);
                ldsm4(al[mt], a2LoB + (size_t)mt * 16 * XST + ck * 32 + kk);
            }
#pragma unroll
            for (int p = 0; p < 4; p++) {
                unsigned t[4], u[4];
                ldsm4(t, sW + bufo + bOff + (size_t)p * 16 * WST + kk);
                ldsm4(u, sW + bufo + 256 * WST + bOff + (size_t)p * 16 * WST + kk);
                unsigned bhA[2] = { t[0], t[1] }, bhB[2] = { t[2], t[3] };
                unsigned blA[2] = { u[0], u[1] }, blB[2] = { u[2], u[3] };
#pragma unroll
                for (int mt = 0; mt < 2; mt++) {
                    mma_bf16(acc[mt][2*p],   ah[mt], bhA);
                    mma_bf16(acc[mt][2*p],   al[mt], bhA);
                    mma_bf16(acc[mt][2*p],   ah[mt], blA);
                    mma_bf16(acc[mt][2*p+1], ah[mt], bhB);
                    mma_bf16(acc[mt][2*p+1], al[mt], bhB);
                    mma_bf16(acc[mt][2*p+1], ah[mt], blB);
                }
            }
        }
        if (ck < 7) { CP_WAIT0(); }
        __syncthreads();
    }

#pragma unroll
    for (int mt = 0; mt < 2; mt++) {
        int r0 = mbase + mt * 16 + g;
#pragma unroll
        for (int nt = 0; nt < 8; nt++) {
            int col = nwarp * 64 + nt * 8 + tq * 2;
            float bb0 = b2[col], bb1 = b2[col + 1];
            unsigned xh = *(const unsigned*)(x1hi + (size_t)r0 * XST + col);
            unsigned xl = *(const unsigned*)(x1lo + (size_t)r0 * XST + col);
            float x0 = __uint_as_float(xh << 16) + __uint_as_float(xl << 16);
            float x1v = __uint_as_float(xh & 0xffff0000u) + __uint_as_float(xl & 0xffff0000u);
            *(float2*)(utmp + (size_t)r0 * VST + col) =
                make_float2(x0 + acc[mt][nt][0] + bb0, x1v + acc[mt][nt][1] + bb1);
            unsigned yh = *(const unsigned*)(x1hi + (size_t)(r0 + 8) * XST + col);
            unsigned yl = *(const unsigned*)(x1lo + (size_t)(r0 + 8) * XST + col);
            float y0 = __uint_as_float(yh << 16) + __uint_as_float(yl << 16);
            float y1 = __uint_as_float(yh & 0xffff0000u) + __uint_as_float(yl & 0xffff0000u);
            *(float2*)(utmp + (size_t)(r0 + 8) * VST + col) =
                make_float2(y0 + acc[mt][nt][2] + bb0, y1 + acc[mt][nt][3] + bb1);
        }
    }
    __syncthreads();

    {
        int r = tid >> 2, q = tid & 3;
        float s1 = 0.f;
#pragma unroll
        for (int i = 0; i < 16; i++) {
            int col = i * 16 + q * 4;
            float4 v = *(float4*)(utmp + (size_t)r * VST + col);
            s1 += v.x + v.y + v.z + v.w;
        }
        s1 += __shfl_xor_sync(0xffffffffu, s1, 1);
        s1 += __shfl_xor_sync(0xffffffffu, s1, 2);
        float mean = s1 * (1.f / 256.f);
        float s2 = 0.f;
#pragma unroll
        for (int i = 0; i < 16; i++) {
            int col = i * 16 + q * 4;
            float4 v = *(float4*)(utmp + (size_t)r * VST + col);
            float dx = v.x - mean, dy = v.y - mean, dz = v.z - mean, dw = v.w - mean;
            s2 += dx * dx + dy * dy + dz * dz + dw * dw;
        }
        s2 += __shfl_xor_sync(0xffffffffu, s2, 1);
        s2 += __shfl_xor_sync(0xffffffffu, s2, 2);
        float rstd = rsqrtf(s2 * (1.f / 256.f) + 1e-5f);
        float* orow = out_x + (size_t)(m0 + r) * 256;
#pragma unroll
        for (int i = 0; i < 16; i++) {
            int col = i * 16 + q * 4;
            float4 v = *(float4*)(utmp + (size_t)r * VST + col);
            float4 gg = *(const float4*)(g2 + col);
            float4 bb = *(const float4*)(be2 + col);
            float4 o4;
            o4.x = (v.x - mean) * rstd * gg.x + bb.x;
            o4.y = (v.y - mean) * rstd * gg.y + bb.y;
            o4.z = (v.z - mean) * rstd * gg.z + bb.z;
            o4.w = (v.w - mean) * rstd * gg.w + bb.w;
            *(float4*)(orow + col) = o4;
        }
    }
}

// ---------------- fused CLS readout tail ----------------------------------
__device__ __forceinline__ float blk_sum256(float v, float* red, int h, int lane) {
#pragma unroll
    for (int o = 16; o; o >>= 1) v += __shfl_xor_sync(0xffffffffu, v, o);
    if (lane == 0) red[h] = v;
    __syncthreads();
    float t = 0.f;
#pragma unroll
    for (int i = 0; i < 8; i++) t += red[i];
    __syncthreads();
    return t;
}

__global__ void __launch_bounds__(256)
cls_tail(const float* __restrict__ CLS, const float* __restrict__ rkv,
         const unsigned char* __restrict__ cmask,
         const float* __restrict__ ro_w1, const float* __restrict__ ro_b1,
         const float* __restrict__ ro_w2, const float* __restrict__ ro_b2,
         const float* __restrict__ rg1, const float* __restrict__ rbe1,
         const float* __restrict__ rg2, const float* __restrict__ rbe2,
         float* __restrict__ out_c) {
    int b = blockIdx.x, tid = threadIdx.x, h = tid >> 5, lane = tid & 31;
    __shared__ float sq[256], c1s[256], h1s[256], red[8];
    __shared__ float sp[8 * 160];

    float clsv = CLS[(size_t)b * 256 + tid];
    sq[tid] = clsv;
    __syncthreads();

    const float scale = 0.17677669529663687f;
    const float* sqh = sq + h * 32;
    float svals[5];
    float smax = -INFINITY;
#pragma unroll
    for (int j = 0; j < 5; j++) {
        int m = lane + j * 32;
        float s = -INFINITY;
        if (m < NT) {
            const float* kr = rkv + (size_t)(b * NT + m) * 512 + h * 32;
            float s0 = 0.f;
#pragma unroll
            for (int d = 0; d < 32; d++) s0 = fmaf(sqh[d], kr[d], s0);
            s = s0 * scale;
            if (cmask[(size_t)b * NT + m]) s = -INFINITY;
        }
        svals[j] = s;
        smax = fmaxf(smax, s);
    }
#pragma unroll
    for (int o = 16; o; o >>= 1)
        smax = fmaxf(smax, __shfl_xor_sync(0xffffffffu, smax, o));
    float ssum = 0.f;
#pragma unroll
    for (int j = 0; j < 5; j++) {
        float p = __expf(svals[j] - smax);
        ssum += p;
        sp[h * 160 + lane + j * 32] = p;
    }
#pragma unroll
    for (int o = 16; o; o >>= 1)
        ssum += __shfl_xor_sync(0xffffffffu, ssum, o);
    __syncwarp();
    float inv = 1.f / ssum;
    float acc = 0.f;
    for (int m = 0; m < NT; m++)
        acc = fmaf(sp[h * 160 + m],
                   rkv[(size_t)(b * NT + m) * 512 + 256 + h * 32 + lane], acc);
    float v = clsv + acc * inv;
    __syncthreads();

    float mean = blk_sum256(v, red, h, lane) * (1.f / 256.f);
    float d = v - mean;
    float var = blk_sum256(d * d, red, h, lane) * (1.f / 256.f);
    float c1 = d * rsqrtf(var + 1e-5f) * rg1[tid] + rbe1[tid];
    c1s[tid] = c1;
    __syncthreads();

    {
        float a2 = 0.f;
        const float4* wr = (const float4*)(ro_w1 + (size_t)tid * 256);
#pragma unroll 8
        for (int i = 0; i < 64; i++) {
            float4 w = wr[i];
            float4 cc = *(const float4*)(c1s + i * 4);
            a2 = fmaf(w.x, cc.x, fmaf(w.y, cc.y, fmaf(w.z, cc.z, fmaf(w.w, cc.w, a2))));
        }
        h1s[tid] = fmaxf(a2 + ro_b1[tid], 0.f);
    }
    __syncthreads();

    float u;
    {
        float a2 = 0.f;
        const float4* wr = (const float4*)(ro_w2 + (size_t)tid * 256);
#pragma unroll 8
        for (int i = 0; i < 64; i++) {
            float4 w = wr[i];
            float4 cc = *(const float4*)(h1s + i * 4);
            a2 = fmaf(w.x, cc.x, fmaf(w.y, cc.y, fmaf(w.z, cc.z, fmaf(w.w, cc.w, a2))));
        }
        u = c1 + a2 + ro_b2[tid];
    }
    float mean2 = blk_sum256(u, red, h, lane) * (1.f / 256.f);
    float d2 = u - mean2;
    float var2 = blk_sum256(d2 * d2, red, h, lane) * (1.f / 256.f);
    out_c[(size_t)b * 256 + tid] = d2 * rsqrtf(var2 + 1e-5f) * rg2[tid] + rbe2[tid];
}

// ---------------- launch --------------------------------------------------
extern "C" void kernel_launch(void* const* d_in, const int* in_sizes, int n_in,
                              void* d_out, int out_size) {
    const float* node_x   = (const float*)d_in[0];
    const float* edge_x   = (const float*)d_in[1];
    const float* CLS      = (const float*)d_in[2];
    const unsigned char* nmask = (const unsigned char*)d_in[3];
    const unsigned char* cmask = (const unsigned char*)d_in[4];
    const float* w_qkv    = (const float*)d_in[5];
    const float* b_qkv    = (const float*)d_in[6];
    const float* w_kve    = (const float*)d_in[7];
    const float* b_kve    = (const float*)d_in[8];
    const float* w1       = (const float*)d_in[9];
    const float* b1       = (const float*)d_in[10];
    const float* w2       = (const float*)d_in[11];
    const float* b2       = (const float*)d_in[12];
    const float* g1       = (const float*)d_in[13];
    const float* be1      = (const float*)d_in[14];
    const float* g2       = (const float*)d_in[15];
    const float* be2      = (const float*)d_in[16];
    const float* ro_w_kv  = (const float*)d_in[17];
    const float* ro_b_kv  = (const float*)d_in[18];
    const float* ro_w1    = (const float*)d_in[19];
    const float* ro_b1    = (const float*)d_in[20];
    const float* ro_w2    = (const float*)d_in[21];
    const float* ro_b2    = (const float*)d_in[22];
    const float* ro_g1    = (const float*)d_in[23];
    const float* ro_be1   = (const float*)d_in[24];
    const float* ro_g2    = (const float*)d_in[25];
    const float* ro_be2   = (const float*)d_in[26];

    float* out_x = (float*)d_out;
    float* out_c = out_x + (size_t)BB * NN * DD;

    float *p_qkv, *p_kve, *p_attn, *p_rkv;
    __nv_bfloat16 *whi, *wlo;
    cudaGetSymbolAddress((void**)&p_qkv,  g_qkv);
    cudaGetSymbolAddress((void**)&p_kve,  g_kve);
    cudaGetSymbolAddress((void**)&p_attn, g_attn);
    cudaGetSymbolAddress((void**)&p_rkv,  g_rkv);
    cudaGetSymbolAddress((void**)&whi,    g_whi);
    cudaGetSymbolAddress((void**)&wlo,    g_wlo);

    cudaFuncSetAttribute(gemm_mma<false, false, true >, cudaFuncAttributeMaxDynamicSharedMemorySize, GEMM_SMEM);
    cudaFuncSetAttribute(gemm_mma<false, true,  false>, cudaFuncAttributeMaxDynamicSharedMemorySize, GEMM_SMEM);
    cudaFuncSetAttribute(attn_flash, cudaFuncAttributeMaxDynamicSharedMemorySize, ATT2_SMEM);
    cudaFuncSetAttribute(ffn_fused, cudaFuncAttributeMaxDynamicSharedMemorySize, FFN_SMEM);

    // fused weight conversion
    conv_all<<<(W_CONV + 255) / 256, 256>>>(w_qkv, w_kve, w1, w2, ro_w_kv, whi, wlo);

    // projections: qkv + edge-kv dual launch.
    // qkv: bx<4 (q,k cols) skip lo-pass; kve: bx<2 (k_e cols) skip.
    gemm_mma<false, false, true><<<6 * 128 + 4 * 256, 256, GEMM_SMEM>>>(
        node_x, edge_x, whi + OFF_QKV, wlo + OFF_QKV, b_qkv, p_qkv, BB * NN, 768,
        whi + OFF_KVE, wlo + OFF_KVE, b_kve, p_kve, BB * EE, 512,
        6 * 128, 6, 4, 4, 2);

    // flash attention (single-pass S)
    attn_flash<<<dim3(HH, BB), 256, ATT2_SMEM>>>(p_qkv, p_kve, nmask, p_attn);

    // fused FFN block
    ffn_fused<<<BB * NN / 64, 256, FFN_SMEM>>>(
        node_x, p_attn,
        whi + OFF_W1, wlo + OFF_W1, whi + OFF_W2, wlo + OFF_W2,
        b1, b2, g1, be1, g2, be2, out_x);

    // readout: rkv — rk cols (bx<2) skip lo-pass, rv cols keep
    gemm_mma<false, true, false><<<dim3(4, 129), 256, GEMM_SMEM>>>(
        out_x, CLS, whi + OFF_ROKV, wlo + OFF_ROKV, ro_b_kv, p_rkv, BB * NT, 512,
        nullptr, nullptr, nullptr, nullptr, 0, 0, 0, 0, 0, 2, 0);

    // fused CLS tail
    cls_tail<<<BB, 256>>>(CLS, p_rkv, cmask, ro_w1, ro_b1, ro_w2, ro_b2,
                          ro_g1, ro_be1, ro_g2, ro_be2, out_c);
}

// round 16
// speedup vs baseline: 1.0699x; 1.0088x over previous
#include <cuda_runtime.h>
#include <cuda_bf16.h>
#include <math.h>

// Shapes
#define BB   64
#define NN   128
#define EE   256
#define DD   256
#define HH   8
#define MT   384   // N + E
#define NT   129   // N + 1

// ---------------- scratch (device globals; no allocation) ----------------
__device__ float g_qkv [BB*NN*3*DD];
__device__ float g_kve [BB*EE*2*DD];
__device__ float g_attn[BB*NN*DD];
__device__ float g_rkv [BB*NT*2*DD];

// bf16 hi/lo weight buffers, layout [Nc][256] (k contiguous)
#define OFF_QKV   0
#define OFF_KVE   (OFF_QKV + 768*256)
#define OFF_W1    (OFF_KVE + 512*256)
#define OFF_W2    (OFF_W1  + 256*256)
#define OFF_ROKV  (OFF_W2  + 256*256)
#define W_CONV    (OFF_ROKV+ 512*256)
__device__ __nv_bfloat16 g_whi[W_CONV];
__device__ __nv_bfloat16 g_wlo[W_CONV];

// ---------------- fused weight conversion (one launch) -------------------
__global__ void conv_all(const float* __restrict__ w_qkv,
                         const float* __restrict__ w_kve,
                         const float* __restrict__ w1,
                         const float* __restrict__ w2,
                         const float* __restrict__ ro_w_kv,
                         __nv_bfloat16* __restrict__ hi,
                         __nv_bfloat16* __restrict__ lo) {
    int i = blockIdx.x * 256 + threadIdx.x;
    if (i >= W_CONV) return;
    const float* W; int Nc; bool direct; int off;
    if      (i < OFF_KVE ) { W = w_qkv;   Nc = 768; direct = false; off = OFF_QKV;  }
    else if (i < OFF_W1  ) { W = w_kve;   Nc = 512; direct = false; off = OFF_KVE;  }
    else if (i < OFF_W2  ) { W = w1;      Nc = 256; direct = true;  off = OFF_W1;   }
    else if (i < OFF_ROKV) { W = w2;      Nc = 256; direct = true;  off = OFF_W2;   }
    else                   { W = ro_w_kv; Nc = 512; direct = false; off = OFF_ROKV; }
    int li = i - off;
    int n = li >> 8, k = li & 255;
    float v = direct ? W[(size_t)n * 256 + k] : W[(size_t)k * Nc + n];
    __nv_bfloat16 h = __float2bfloat16(v);
    hi[i] = h;
    lo[i] = __float2bfloat16(v - __bfloat162float(h));
}

// ---------------- mma / ldmatrix / cp.async helpers -----------------------
__device__ __forceinline__ void mma_bf16(float* c, const unsigned* a, const unsigned* b) {
    asm volatile(
        "mma.sync.aligned.m16n8k16.row.col.f32.bf16.bf16.f32 "
        "{%0,%1,%2,%3}, {%4,%5,%6,%7}, {%8,%9}, {%0,%1,%2,%3};\n"
        : "+f"(c[0]), "+f"(c[1]), "+f"(c[2]), "+f"(c[3])
        : "r"(a[0]), "r"(a[1]), "r"(a[2]), "r"(a[3]), "r"(b[0]), "r"(b[1]));
}

__device__ __forceinline__ void ldsm4(unsigned* r, const void* p) {
    unsigned a = (unsigned)__cvta_generic_to_shared(p);
    asm volatile("ldmatrix.sync.aligned.m8n8.x4.shared.b16 {%0,%1,%2,%3}, [%4];"
                 : "=r"(r[0]), "=r"(r[1]), "=r"(r[2]), "=r"(r[3]) : "r"(a));
}

__device__ __forceinline__ void cpa16(void* s, const void* g) {
    unsigned a = (unsigned)__cvta_generic_to_shared(s);
    asm volatile("cp.async.cg.shared.global [%0], [%1], 16;" :: "r"(a), "l"(g));
}
#define CP_COMMIT() asm volatile("cp.async.commit_group;" ::: "memory")
#define CP_WAIT0()  asm volatile("cp.async.wait_group 0;" ::: "memory")

// packed-cvt hi/lo split: low half = x, high half = y
__device__ __forceinline__ void split2(float x, float y, unsigned& hi, unsigned& lo) {
    unsigned h;
    asm("cvt.rn.bf16x2.f32 %0, %1, %2;" : "=r"(h) : "f"(y), "f"(x));
    float fx = __uint_as_float(h << 16);
    float fy = __uint_as_float(h & 0xffff0000u);
    unsigned l;
    asm("cvt.rn.bf16x2.f32 %0, %1, %2;" : "=r"(l) : "f"(y - fy), "f"(x - fx));
    hi = h; lo = l;
}

__device__ __forceinline__ unsigned pack_bf16(float x, float y) {
    unsigned h;
    asm("cvt.rn.bf16x2.f32 %0, %1, %2;" : "=r"(h) : "f"(y), "f"(x));
    return h;
}

#define GST 72   // smem row stride in bf16 (144B)
// A hi/lo double-buffered + B hi/lo double-buffered
#define GEMM_SMEM ((4*64*GST + 4*128*GST) * (int)sizeof(__nv_bfloat16))   // 110592

// ---------------- bf16-split tensor-core GEMM (BM=64, pipelined) ----------
// A double-buffered in smem -> ONE sync per k-chunk.
// nskip: n-blocks with bx < nskip drop the ah*bl pass (score-path columns)
template<bool RELU, bool CONCAT, bool DUAL>
__global__ void __launch_bounds__(256)
gemm_mma(const float* __restrict__ A, const float* __restrict__ A2,
         const __nv_bfloat16* __restrict__ Whi,
         const __nv_bfloat16* __restrict__ Wlo,
         const float* __restrict__ bias,
         float* __restrict__ C, int M, int Nc,
         const __nv_bfloat16* Whi2, const __nv_bfloat16* Wlo2,
         const float* bias2, float* C2, int M2, int Nc2,
         int nb0, int gx0, int gx1, int nskip0, int nskip1) {
    extern __shared__ __nv_bfloat16 sm[];
    __nv_bfloat16* sAhi = sm;                       // 2 buffers
    __nv_bfloat16* sAlo = sAhi + 2 * 64 * GST;      // 2 buffers
    __nv_bfloat16* sBhi = sAlo + 2 * 64 * GST;      // 2 buffers
    __nv_bfloat16* sBlo = sBhi + 2 * 128 * GST;     // 2 buffers

    int bx, by;
    const float* Ap = A;
    const __nv_bfloat16* Whip = Whi;
    const __nv_bfloat16* Wlop = Wlo;
    const float* biasp = bias;
    float* Cp = C;
    int Mp = M, Ncp = Nc, nskip = nskip0;
    if (DUAL) {
        int bid = blockIdx.x;
        if (bid < nb0) { bx = bid % gx0; by = bid / gx0; }
        else {
            bid -= nb0; bx = bid % gx1; by = bid / gx1;
            Ap = A2; Whip = Whi2; Wlop = Wlo2; biasp = bias2; Cp = C2;
            Mp = M2; Ncp = Nc2; nskip = nskip1;
        }
    } else {
        bx = blockIdx.x; by = blockIdx.y;
    }
    bool uselo = bx >= nskip;

    int tid = threadIdx.x;
    int lane = tid & 31, warp = tid >> 5;
    int g = lane >> 2, tq = lane & 3;
    int mbase = (warp >> 2) * 32;
    int nbase = (warp & 3) * 32;
    int m0 = by * 64;
    int n0 = bx * 128;

    int lr = lane & 7, sel = lane >> 3;
    size_t aOff = (size_t)(mbase + (sel & 1) * 8 + lr) * GST + ((sel >> 1) & 1) * 8;
    size_t bOff = (size_t)(nbase + (sel >> 1) * 8 + lr) * GST + (sel & 1) * 8;

    int ar = tid >> 2, aq = tid & 3;
    int arr = m0 + ar;
    bool avalid = arr < Mp;
    const float* aRow;
    if (CONCAT) {
        int bidx = arr / NT, t = arr - bidx * NT;
        aRow = (t == 0) ? A2 + (size_t)bidx * 256
                        : Ap + (size_t)(bidx * NN + t - 1) * 256;
    } else {
        aRow = Ap + (size_t)arr * 256;
    }
    int colb = aq * 16;
    aRow += colb;

    int bn = tid >> 1, bck = (tid & 1) * 32;

    float acc[2][4][4];
#pragma unroll
    for (int mt = 0; mt < 2; mt++)
#pragma unroll
        for (int nt = 0; nt < 4; nt++)
#pragma unroll
            for (int i = 0; i < 4; i++) acc[mt][nt][i] = 0.f;

    float4 av[4];
    // ---- prologue: B0 via cp.async; A0 via regs -> Abuf0 ----
    {
        const __nv_bfloat16* wh = Whip + (size_t)(n0 + bn) * 256 + bck;
        const __nv_bfloat16* wl = Wlop + (size_t)(n0 + bn) * 256 + bck;
        __nv_bfloat16* dh = sBhi + (size_t)bn * GST + bck;
        __nv_bfloat16* dl = sBlo + (size_t)bn * GST + bck;
#pragma unroll
        for (int i = 0; i < 4; i++) {
            cpa16(dh + i * 8, wh + i * 8);
            cpa16(dl + i * 8, wl + i * 8);
        }
        CP_COMMIT();
#pragma unroll
        for (int i = 0; i < 4; i++)
            av[i] = avalid ? *(const float4*)(aRow + i * 4)
                           : make_float4(0.f, 0.f, 0.f, 0.f);
#pragma unroll
        for (int i = 0; i < 4; i++) {
            unsigned h01, l01, h23, l23;
            split2(av[i].x, av[i].y, h01, l01);
            split2(av[i].z, av[i].w, h23, l23);
            int c = colb + i * 4;
            *(unsigned*)(sAhi + (size_t)ar * GST + c)     = h01;
            *(unsigned*)(sAhi + (size_t)ar * GST + c + 2) = h23;
            *(unsigned*)(sAlo + (size_t)ar * GST + c)     = l01;
            *(unsigned*)(sAlo + (size_t)ar * GST + c + 2) = l23;
        }
        CP_WAIT0();
        __syncthreads();
    }

    for (int it = 0; it < 4; it++) {
        int nk = it + 1;
        if (nk < 4) {
            int buf = nk & 1;
            const __nv_bfloat16* wh = Whip + (size_t)(n0 + bn) * 256 + nk * 64 + bck;
            const __nv_bfloat16* wl = Wlop + (size_t)(n0 + bn) * 256 + nk * 64 + bck;
            __nv_bfloat16* dh = sBhi + (size_t)buf * 128 * GST + (size_t)bn * GST + bck;
            __nv_bfloat16* dl = sBlo + (size_t)buf * 128 * GST + (size_t)bn * GST + bck;
#pragma unroll
            for (int i = 0; i < 4; i++) {
                cpa16(dh + i * 8, wh + i * 8);
                cpa16(dl + i * 8, wl + i * 8);
            }
            CP_COMMIT();
#pragma unroll
            for (int i = 0; i < 4; i++)
                av[i] = avalid ? *(const float4*)(aRow + nk * 64 + i * 4)
                               : make_float4(0.f, 0.f, 0.f, 0.f);
        }

        // ---- compute on Abuf[it&1] + Bbuf[it&1] ----
        {
            size_t abufo = (size_t)(it & 1) * 64 * GST;
            size_t bbufo = (size_t)(it & 1) * 128 * GST;
            const __nv_bfloat16* aHiB = sAhi + abufo + aOff;
            const __nv_bfloat16* aLoB = sAlo + abufo + aOff;
            const __nv_bfloat16* bHiB = sBhi + bbufo + bOff;
            const __nv_bfloat16* bLoB = sBlo + bbufo + bOff;
#pragma unroll
            for (int kk = 0; kk < 64; kk += 16) {
                unsigned ah[2][4], al[2][4], bh[4][2], bl[4][2];
#pragma unroll
                for (int mt = 0; mt < 2; mt++) {
                    ldsm4(ah[mt], aHiB + (size_t)mt * 16 * GST + kk);
                    ldsm4(al[mt], aLoB + (size_t)mt * 16 * GST + kk);
                }
#pragma unroll
                for (int p = 0; p < 2; p++) {
                    unsigned t[4];
                    ldsm4(t, bHiB + (size_t)p * 16 * GST + kk);
                    bh[2*p][0] = t[0]; bh[2*p][1] = t[1];
                    bh[2*p+1][0] = t[2]; bh[2*p+1][1] = t[3];
                    ldsm4(t, bLoB + (size_t)p * 16 * GST + kk);
                    bl[2*p][0] = t[0]; bl[2*p][1] = t[1];
                    bl[2*p+1][0] = t[2]; bl[2*p+1][1] = t[3];
                }
#pragma unroll
                for (int mt = 0; mt < 2; mt++)
#pragma unroll
                    for (int nt = 0; nt < 4; nt++) {
                        mma_bf16(acc[mt][nt], ah[mt], bh[nt]);
                        mma_bf16(acc[mt][nt], al[mt], bh[nt]);
                        if (uselo) mma_bf16(acc[mt][nt], ah[mt], bl[nt]);
                    }
            }
        }
        if (nk < 4) {
            // store A(nk) into the OTHER A buffer (no hazard with ongoing reads)
            size_t abufo = (size_t)(nk & 1) * 64 * GST;
#pragma unroll
            for (int i = 0; i < 4; i++) {
                unsigned h01, l01, h23, l23;
                split2(av[i].x, av[i].y, h01, l01);
                split2(av[i].z, av[i].w, h23, l23);
                int c = colb + i * 4;
                *(unsigned*)(sAhi + abufo + (size_t)ar * GST + c)     = h01;
                *(unsigned*)(sAhi + abufo + (size_t)ar * GST + c + 2) = h23;
                *(unsigned*)(sAlo + abufo + (size_t)ar * GST + c)     = l01;
                *(unsigned*)(sAlo + abufo + (size_t)ar * GST + c + 2) = l23;
            }
            CP_WAIT0();
            __syncthreads();   // single barrier per chunk
        }
    }

#pragma unroll
    for (int mt = 0; mt < 2; mt++) {
        int r0 = m0 + mbase + mt * 16 + g;
#pragma unroll
        for (int nt = 0; nt < 4; nt++) {
            int col = n0 + nbase + nt * 8 + tq * 2;
            float b0 = biasp[col], b1 = biasp[col + 1];
            if (r0 < Mp) {
                float v0 = acc[mt][nt][0] + b0;
                float v1 = acc[mt][nt][1] + b1;
                if (RELU) { v0 = fmaxf(v0, 0.f); v1 = fmaxf(v1, 0.f); }
                Cp[(size_t)r0 * Ncp + col]     = v0;
                Cp[(size_t)r0 * Ncp + col + 1] = v1;
            }
            if (r0 + 8 < Mp) {
                float v2 = acc[mt][nt][2] + b0;
                float v3 = acc[mt][nt][3] + b1;
                if (RELU) { v2 = fmaxf(v2, 0.f); v3 = fmaxf(v3, 0.f); }
                Cp[(size_t)(r0 + 8) * Ncp + col]     = v2;
                Cp[(size_t)(r0 + 8) * Ncp + col + 1] = v3;
            }
        }
    }
}

// ---------------- flash attention on tensor cores -------------------------
// S: single-pass q_hi @ K_hi. P@V: full 3-pass hi/lo.
#define AK_STR 40
#define AV_STR 392
#define ATT2_SMEM ((384*AK_STR + 2*32*AV_STR) * (int)sizeof(__nv_bfloat16))

__global__ void __launch_bounds__(256, 2)
attn_flash(const float* __restrict__ qkv,
           const float* __restrict__ kve,
           const unsigned char* __restrict__ nmask,
           float* __restrict__ out) {
    int h = blockIdx.x, b = blockIdx.y;
    extern __shared__ __nv_bfloat16 smb[];
    __nv_bfloat16* Khi  = smb;
    __nv_bfloat16* Vthi = Khi  + 384 * AK_STR;
    __nv_bfloat16* Vtlo = Vthi + 32 * AV_STR;

    int tid = threadIdx.x;
    for (int idx = tid; idx < MT * 8; idx += 256) {
        int m = idx >> 3, d4 = (idx & 7) * 4;
        float4 kv4, vv4;
        if (m < NN) {
            const float* base = qkv + (size_t)(b * NN + m) * 768 + h * 32 + d4;
            kv4 = *(const float4*)(base + 256);
            vv4 = *(const float4*)(base + 512);
        } else {
            const float* base = kve + (size_t)(b * EE + (m - NN)) * 512 + h * 32 + d4;
            kv4 = *(const float4*)(base);
            vv4 = *(const float4*)(base + 256);
        }
        *(unsigned*)(Khi + m * AK_STR + d4)     = pack_bf16(kv4.x, kv4.y);
        *(unsigned*)(Khi + m * AK_STR + d4 + 2) = pack_bf16(kv4.z, kv4.w);
        float vs[4] = { vv4.x, vv4.y, vv4.z, vv4.w };
#pragma unroll
        for (int j = 0; j < 4; j++) {
            __nv_bfloat16 vh = __float2bfloat16(vs[j]);
            Vthi[(d4 + j) * AV_STR + m] = vh;
            Vtlo[(d4 + j) * AV_STR + m] = __float2bfloat16(vs[j] - __bfloat162float(vh));
        }
    }
    __syncthreads();

    int lane = tid & 31, warp = tid >> 5;
    int g = lane >> 2, tq = lane & 3;
    int lr = lane & 7, sel = lane >> 3;
    int r0 = warp * 16 + g;
    int r1 = r0 + 8;
    const float scale = 0.17677669529663687f;

    const __nv_bfloat16* kHiB = Khi  + (size_t)((sel >> 1) * 8 + lr) * AK_STR + (sel & 1) * 8;
    const __nv_bfloat16* vHiB = Vthi + (size_t)((sel >> 1) * 8 + lr) * AV_STR + (sel & 1) * 8;
    const __nv_bfloat16* vLoB = Vtlo + (size_t)((sel >> 1) * 8 + lr) * AV_STR + (sel & 1) * 8;

    unsigned qh[2][4];
    {
        const float* q0p = qkv + (size_t)(b * NN + r0) * 768 + h * 32;
        const float* q1p = qkv + (size_t)(b * NN + r1) * 768 + h * 32;
#pragma unroll
        for (int kk2 = 0; kk2 < 2; kk2++) {
            int kb = kk2 * 16 + tq * 2;
            float2 v;
            v = *(const float2*)(q0p + kb);
            qh[kk2][0] = pack_bf16(v.x * scale, v.y * scale);
            v = *(const float2*)(q1p + kb);
            qh[kk2][1] = pack_bf16(v.x * scale, v.y * scale);
            v = *(const float2*)(q0p + kb + 8);
            qh[kk2][2] = pack_bf16(v.x * scale, v.y * scale);
            v = *(const float2*)(q1p + kb + 8);
            qh[kk2][3] = pack_bf16(v.x * scale, v.y * scale);
        }
    }

    const unsigned short* mrow0 =
        (const unsigned short*)(nmask + (size_t)(b * NN + r0) * MT);
    const unsigned short* mrow1 =
        (const unsigned short*)(nmask + (size_t)(b * NN + r1) * MT);

    float m0 = -INFINITY, m1 = -INFINITY, l0 = 0.f, l1 = 0.f;
    float o[4][4];
#pragma unroll
    for (int nt = 0; nt < 4; nt++)
#pragma unroll
        for (int i = 0; i < 4; i++) o[nt][i] = 0.f;

#pragma unroll
    for (int c = 0; c < 6; c++) {
        int tkb = c * 64;
        float s[8][4];
#pragma unroll
        for (int nt = 0; nt < 8; nt++)
#pragma unroll
            for (int i = 0; i < 4; i++) s[nt][i] = 0.f;

#pragma unroll
        for (int kk2 = 0; kk2 < 2; kk2++) {
#pragma unroll
            for (int p = 0; p < 4; p++) {
                unsigned t[4];
                ldsm4(t, kHiB + (size_t)(tkb + p * 16) * AK_STR + kk2 * 16);
                unsigned bhA[2] = { t[0], t[1] }, bhB[2] = { t[2], t[3] };
                mma_bf16(s[2*p],   qh[kk2], bhA);
                mma_bf16(s[2*p+1], qh[kk2], bhB);
            }
        }

        float cm0 = -INFINITY, cm1 = -INFINITY;
#pragma unroll
        for (int nt = 0; nt < 8; nt++) {
            int t = tkb + nt * 8 + tq * 2;
            unsigned short mm0 = mrow0[t >> 1];
            unsigned short mm1 = mrow1[t >> 1];
            if (mm0 & 0x00FFu) s[nt][0] = -INFINITY;
            if (mm0 & 0xFF00u) s[nt][1] = -INFINITY;
            if (mm1 & 0x00FFu) s[nt][2] = -INFINITY;
            if (mm1 & 0xFF00u) s[nt][3] = -INFINITY;
            cm0 = fmaxf(cm0, fmaxf(s[nt][0], s[nt][1]));
            cm1 = fmaxf(cm1, fmaxf(s[nt][2], s[nt][3]));
        }
        cm0 = fmaxf(cm0, __shfl_xor_sync(0xffffffffu, cm0, 1));
        cm0 = fmaxf(cm0, __shfl_xor_sync(0xffffffffu, cm0, 2));
        cm1 = fmaxf(cm1, __shfl_xor_sync(0xffffffffu, cm1, 1));
        cm1 = fmaxf(cm1, __shfl_xor_sync(0xffffffffu, cm1, 2));

        float nm0 = fmaxf(m0, cm0), nm1 = fmaxf(m1, cm1);
        float corr0 = (m0 == -INFINITY) ? 0.f : __expf(m0 - nm0);
        float corr1 = (m1 == -INFINITY) ? 0.f : __expf(m1 - nm1);
        float e0 = (nm0 == -INFINITY) ? 0.f : nm0;
        float e1 = (nm1 == -INFINITY) ? 0.f : nm1;
        m0 = nm0; m1 = nm1;
        l0 *= corr0; l1 *= corr1;
#pragma unroll
        for (int nt = 0; nt < 4; nt++) {
            o[nt][0] *= corr0; o[nt][1] *= corr0;
            o[nt][2] *= corr1; o[nt][3] *= corr1;
        }

#pragma unroll
        for (int ks = 0; ks < 4; ks++) {
            float p00 = __expf(s[2*ks][0]   - e0);
            float p01 = __expf(s[2*ks][1]   - e0);
            float p02 = __expf(s[2*ks][2]   - e1);
            float p03 = __expf(s[2*ks][3]   - e1);
            float p10 = __expf(s[2*ks+1][0] - e0);
            float p11 = __expf(s[2*ks+1][1] - e0);
            float p12 = __expf(s[2*ks+1][2] - e1);
            float p13 = __expf(s[2*ks+1][3] - e1);
            l0 += p00 + p01 + p10 + p11;
            l1 += p02 + p03 + p12 + p13;
            unsigned ah[4], al[4];
            split2(p00, p01, ah[0], al[0]);
            split2(p02, p03, ah[1], al[1]);
            split2(p10, p11, ah[2], al[2]);
            split2(p12, p13, ah[3], al[3]);
#pragma unroll
            for (int p = 0; p < 2; p++) {
                unsigned t[4], u[4];
                ldsm4(t, vHiB + (size_t)p * 16 * AV_STR + tkb + ks * 16);
                ldsm4(u, vLoB + (size_t)p * 16 * AV_STR + tkb + ks * 16);
                unsigned bhA[2] = { t[0], t[1] }, bhB[2] = { t[2], t[3] };
                unsigned blA[2] = { u[0], u[1] }, blB[2] = { u[2], u[3] };
                mma_bf16(o[2*p],   ah, bhA);
                mma_bf16(o[2*p],   al, bhA);
                mma_bf16(o[2*p],   ah, blA);
                mma_bf16(o[2*p+1], ah, bhB);
                mma_bf16(o[2*p+1], al, bhB);
                mma_bf16(o[2*p+1], ah, blB);
            }
        }
    }

    l0 += __shfl_xor_sync(0xffffffffu, l0, 1);
    l0 += __shfl_xor_sync(0xffffffffu, l0, 2);
    l1 += __shfl_xor_sync(0xffffffffu, l1, 1);
    l1 += __shfl_xor_sync(0xffffffffu, l1, 2);
    float inv0 = 1.f / l0, inv1 = 1.f / l1;
    size_t ob0 = (size_t)(b * NN + r0) * DD + h * 32;
    size_t ob1 = (size_t)(b * NN + r1) * DD + h * 32;
#pragma unroll
    for (int nt = 0; nt < 4; nt++) {
        int dcol = nt * 8 + tq * 2;
        *(float2*)(out + ob0 + dcol) = make_float2(o[nt][0] * inv0, o[nt][1] * inv0);
        *(float2*)(out + ob1 + dcol) = make_float2(o[nt][2] * inv1, o[nt][3] * inv1);
    }
}

// ---------------- fused FFN megakernel (256 threads — proven) -------------
#define XST 264
#define WST 40
#define VST 260
#define FFN_SMEM ((4*64*XST + 2*2*256*WST) * (int)sizeof(__nv_bfloat16))  // 217088

__global__ void __launch_bounds__(256)
ffn_fused(const float* __restrict__ nx, const float* __restrict__ at,
          const __nv_bfloat16* __restrict__ w1hi, const __nv_bfloat16* __restrict__ w1lo,
          const __nv_bfloat16* __restrict__ w2hi, const __nv_bfloat16* __restrict__ w2lo,
          const float* __restrict__ b1, const float* __restrict__ b2,
          const float* __restrict__ g1, const float* __restrict__ be1,
          const float* __restrict__ g2, const float* __restrict__ be2,
          float* __restrict__ out_x) {
    extern __shared__ __nv_bfloat16 sm[];
    __nv_bfloat16* x1hi = sm;
    __nv_bfloat16* x1lo = x1hi + 64 * XST;
    __nv_bfloat16* h1hi = x1lo + 64 * XST;
    __nv_bfloat16* h1lo = h1hi + 64 * XST;
    __nv_bfloat16* sW   = h1lo + 64 * XST;
    float* vtmp = (float*)h1hi;
    float* utmp = (float*)sW;

    int tid = threadIdx.x;
    int lane = tid & 31, warp = tid >> 5;
    int g = lane >> 2, tq = lane & 3;
    int lr = lane & 7, sel = lane >> 3;
    int mbase = (warp >> 2) * 32;
    int nwarp = warp & 3;
    int m0 = blockIdx.x * 64;

    {
        const __nv_bfloat16* wh = w1hi + (size_t)tid * 256;
        const __nv_bfloat16* wl = w1lo + (size_t)tid * 256;
        __nv_bfloat16* dh = sW + (size_t)tid * WST;
        __nv_bfloat16* dl = sW + 256 * WST + (size_t)tid * WST;
#pragma unroll
        for (int i = 0; i < 4; i++) { cpa16(dh + i * 8, wh + i * 8); cpa16(dl + i * 8, wl + i * 8); }
        CP_COMMIT();
    }

    {
        int r = tid >> 2, q = tid & 3;
        const float* nrow = nx + (size_t)(m0 + r) * 256;
        const float* arow = at + (size_t)(m0 + r) * 256;
        float s1 = 0.f;
#pragma unroll
        for (int i = 0; i < 16; i++) {
            int col = i * 16 + q * 4;
            float4 v = *(const float4*)(nrow + col);
            float4 a = *(const float4*)(arow + col);
            v.x += a.x; v.y += a.y; v.z += a.z; v.w += a.w;
            *(float4*)(vtmp + (size_t)r * VST + col) = v;
            s1 += v.x + v.y + v.z + v.w;
        }
        s1 += __shfl_xor_sync(0xffffffffu, s1, 1);
        s1 += __shfl_xor_sync(0xffffffffu, s1, 2);
        float mean = s1 * (1.f / 256.f);
        float s2 = 0.f;
#pragma unroll
        for (int i = 0; i < 16; i++) {
            int col = i * 16 + q * 4;
            float4 v = *(float4*)(vtmp + (size_t)r * VST + col);
            v.x -= mean; v.y -= mean; v.z -= mean; v.w -= mean;
            *(float4*)(vtmp + (size_t)r * VST + col) = v;
            s2 += v.x * v.x + v.y * v.y + v.z * v.z + v.w * v.w;
        }
        s2 += __shfl_xor_sync(0xffffffffu, s2, 1);
        s2 += __shfl_xor_sync(0xffffffffu, s2, 2);
        float rstd = rsqrtf(s2 * (1.f / 256.f) + 1e-5f);
#pragma unroll
        for (int i = 0; i < 16; i++) {
            int col = i * 16 + q * 4;
            float4 v = *(float4*)(vtmp + (size_t)r * VST + col);
            float4 gg = *(const float4*)(g1 + col);
            float4 bb = *(const float4*)(be1 + col);
            float x0 = v.x * rstd * gg.x + bb.x;
            float x1 = v.y * rstd * gg.y + bb.y;
            float x2 = v.z * rstd * gg.z + bb.z;
            float x3 = v.w * rstd * gg.w + bb.w;
            unsigned h01, l01, h23, l23;
            split2(x0, x1, h01, l01);
            split2(x2, x3, h23, l23);
            *(unsigned*)(x1hi + (size_t)r * XST + col)     = h01;
            *(unsigned*)(x1hi + (size_t)r * XST + col + 2) = h23;
            *(unsigned*)(x1lo + (size_t)r * XST + col)     = l01;
            *(unsigned*)(x1lo + (size_t)r * XST + col + 2) = l23;
        }
    }
    CP_WAIT0();
    __syncthreads();

    const __nv_bfloat16* a1HiB = x1hi + (size_t)(mbase + (sel & 1) * 8 + lr) * XST + ((sel >> 1) & 1) * 8;
    const __nv_bfloat16* a1LoB = x1lo + (size_t)(mbase + (sel & 1) * 8 + lr) * XST + ((sel >> 1) & 1) * 8;
    const __nv_bfloat16* a2HiB = h1hi + (size_t)(mbase + (sel & 1) * 8 + lr) * XST + ((sel >> 1) & 1) * 8;
    const __nv_bfloat16* a2LoB = h1lo + (size_t)(mbase + (sel & 1) * 8 + lr) * XST + ((sel >> 1) & 1) * 8;
    size_t bOff = (size_t)(nwarp * 64 + (sel >> 1) * 8 + lr) * WST + (sel & 1) * 8;

    float acc[2][8][4];
#pragma unroll
    for (int mt = 0; mt < 2; mt++)
#pragma unroll
        for (int nt = 0; nt < 8; nt++)
#pragma unroll
            for (int i = 0; i < 4; i++) acc[mt][nt][i] = 0.f;

#pragma unroll
    for (int ck = 0; ck < 8; ck++) {
        if (ck < 7) {
            int buf = (ck + 1) & 1;
            const __nv_bfloat16* wh = w1hi + (size_t)tid * 256 + (ck + 1) * 32;
            const __nv_bfloat16* wl = w1lo + (size_t)tid * 256 + (ck + 1) * 32;
            __nv_bfloat16* dh = sW + (size_t)buf * 2 * 256 * WST + (size_t)tid * WST;
            __nv_bfloat16* dl = dh + 256 * WST;
#pragma unroll
            for (int i = 0; i < 4; i++) { cpa16(dh + i * 8, wh + i * 8); cpa16(dl + i * 8, wl + i * 8); }
            CP_COMMIT();
        }
        size_t bufo = (size_t)(ck & 1) * 2 * 256 * WST;
#pragma unroll
        for (int kk = 0; kk < 32; kk += 16) {
            unsigned ah[2][4], al[2][4];
#pragma unroll
            for (int mt = 0; mt < 2; mt++) {
                ldsm4(ah[mt], a1HiB + (size_t)mt * 16 * XST + ck * 32 + kk);
                ldsm4(al[mt], a1LoB + (size_t)mt * 16 * XST + ck * 32 + kk);
            }
#pragma unroll
            for (int p = 0; p < 4; p++) {
                unsigned t[4], u[4];
                ldsm4(t, sW + bufo + bOff + (size_t)p * 16 * WST + kk);
                ldsm4(u, sW + bufo + 256 * WST + bOff + (size_t)p * 16 * WST + kk);
                unsigned bhA[2] = { t[0], t[1] }, bhB[2] = { t[2], t[3] };
                unsigned blA[2] = { u[0], u[1] }, blB[2] = { u[2], u[3] };
#pragma unroll
                for (int mt = 0; mt < 2; mt++) {
                    mma_bf16(acc[mt][2*p],   ah[mt], bhA);
                    mma_bf16(acc[mt][2*p],   al[mt], bhA);
                    mma_bf16(acc[mt][2*p],   ah[mt], blA);
                    mma_bf16(acc[mt][2*p+1], ah[mt], bhB);
                    mma_bf16(acc[mt][2*p+1], al[mt], bhB);
                    mma_bf16(acc[mt][2*p+1], ah[mt], blB);
                }
            }
        }
        if (ck < 7) { CP_WAIT0(); }
        __syncthreads();
    }

    {
        const __nv_bfloat16* wh = w2hi + (size_t)tid * 256;
        const __nv_bfloat16* wl = w2lo + (size_t)tid * 256;
        __nv_bfloat16* dh = sW + (size_t)tid * WST;
        __nv_bfloat16* dl = sW + 256 * WST + (size_t)tid * WST;
#pragma unroll
        for (int i = 0; i < 4; i++) { cpa16(dh + i * 8, wh + i * 8); cpa16(dl + i * 8, wl + i * 8); }
        CP_COMMIT();
    }

#pragma unroll
    for (int mt = 0; mt < 2; mt++) {
        int r0 = mbase + mt * 16 + g;
#pragma unroll
        for (int nt = 0; nt < 8; nt++) {
            int col = nwarp * 64 + nt * 8 + tq * 2;
            float bb0 = b1[col], bb1 = b1[col + 1];
            float v0 = fmaxf(acc[mt][nt][0] + bb0, 0.f);
            float v1 = fmaxf(acc[mt][nt][1] + bb1, 0.f);
            float v2 = fmaxf(acc[mt][nt][2] + bb0, 0.f);
            float v3 = fmaxf(acc[mt][nt][3] + bb1, 0.f);
            unsigned h01, l01, h23, l23;
            split2(v0, v1, h01, l01);
            split2(v2, v3, h23, l23);
            *(unsigned*)(h1hi + (size_t)r0 * XST + col)       = h01;
            *(unsigned*)(h1lo + (size_t)r0 * XST + col)       = l01;
            *(unsigned*)(h1hi + (size_t)(r0 + 8) * XST + col) = h23;
            *(unsigned*)(h1lo + (size_t)(r0 + 8) * XST + col) = l23;
            acc[mt][nt][0] = 0.f; acc[mt][nt][1] = 0.f;
            acc[mt][nt][2] = 0.f; acc[mt][nt][3] = 0.f;
        }
    }
    CP_WAIT0();
    __syncthreads();

#pragma unroll
    for (int ck = 0; ck < 8; ck++) {
        if (ck < 7) {
            int buf = (ck + 1) & 1;
            const __nv_bfloat16* wh = w2hi + (size_t)tid * 256 + (ck + 1) * 32;
            const __nv_bfloat16* wl = w2lo + (size_t)tid * 256 + (ck + 1) * 32;
            __nv_bfloat16* dh = sW + (size_t)buf * 2 * 256 * WST + (size_t)tid * WST;
            __nv_bfloat16* dl = dh + 256 * WST;
#pragma unroll
            for (int i = 0; i < 4; i++) { cpa16(dh + i * 8, wh + i * 8); cpa16(dl + i * 8, wl + i * 8); }
            CP_COMMIT();
        }
        size_t bufo = (size_t)(ck & 1) * 2 * 256 * WST;
#pragma unroll
        for (int kk = 0; kk < 32; kk += 16) {
            unsigned ah[2][4], al[2][4];
#pragma unroll
            for (int mt = 0; mt < 2; mt++) {
                ldsm4(ah[mt], a2HiB + (size_t)mt * 16 * XST + ck * 32 + kk);
                ldsm4(al[mt], a2LoB + (size_t)mt * 16 * XST + ck * 32 + kk);
            }
#pragma unroll
            for (int p = 0; p < 4; p++) {
                unsigned t[4], u[4];
                ldsm4(t, sW + bufo + bOff + (size_t)p * 16 * WST + kk);
                ldsm4(u, sW + bufo + 256 * WST + bOff + (size_t)p * 16 * WST + kk);
                unsigned bhA[2] = { t[0], t[1] }, bhB[2] = { t[2], t[3] };
                unsigned blA[2] = { u[0], u[1] }, blB[2] = { u[2], u[3] };
#pragma unroll
                for (int mt = 0; mt < 2; mt++) {
                    mma_bf16(acc[mt][2*p],   ah[mt], bhA);
                    mma_bf16(acc[mt][2*p],   al[mt], bhA);
                    mma_bf16(acc[mt][2*p],   ah[mt], blA);
                    mma_bf16(acc[mt][2*p+1], ah[mt], bhB);
                    mma_bf16(acc[mt][2*p+1], al[mt], bhB);
                    mma_bf16(acc[mt][2*p+1], ah[mt], blB);
                }
            }
        }
        if (ck < 7) { CP_WAIT0(); }
        __syncthreads();
    }

#pragma unroll
    for (int mt = 0; mt < 2; mt++) {
        int r0 = mbase + mt * 16 + g;
#pragma unroll
        for (int nt = 0; nt < 8; nt++) {
            int col = nwarp * 64 + nt * 8 + tq * 2;
            float bb0 = b2[col], bb1 = b2[col + 1];
            unsigned xh = *(const unsigned*)(x1hi + (size_t)r0 * XST + col);
            unsigned xl = *(const unsigned*)(x1lo + (size_t)r0 * XST + col);
            float x0 = __uint_as_float(xh << 16) + __uint_as_float(xl << 16);
            float x1v = __uint_as_float(xh & 0xffff0000u) + __uint_as_float(xl & 0xffff0000u);
            *(float2*)(utmp + (size_t)r0 * VST + col) =
                make_float2(x0 + acc[mt][nt][0] + bb0, x1v + acc[mt][nt][1] + bb1);
            unsigned yh = *(const unsigned*)(x1hi + (size_t)(r0 + 8) * XST + col);
            unsigned yl = *(const unsigned*)(x1lo + (size_t)(r0 + 8) * XST + col);
            float y0 = __uint_as_float(yh << 16) + __uint_as_float(yl << 16);
            float y1 = __uint_as_float(yh & 0xffff0000u) + __uint_as_float(yl & 0xffff0000u);
            *(float2*)(utmp + (size_t)(r0 + 8) * VST + col) =
                make_float2(y0 + acc[mt][nt][2] + bb0, y1 + acc[mt][nt][3] + bb1);
        }
    }
    __syncthreads();

    {
        int r = tid >> 2, q = tid & 3;
        float s1 = 0.f;
#pragma unroll
        for (int i = 0; i < 16; i++) {
            int col = i * 16 + q * 4;
            float4 v = *(float4*)(utmp + (size_t)r * VST + col);
            s1 += v.x + v.y + v.z + v.w;
        }
        s1 += __shfl_xor_sync(0xffffffffu, s1, 1);
        s1 += __shfl_xor_sync(0xffffffffu, s1, 2);
        float mean = s1 * (1.f / 256.f);
        float s2 = 0.f;
#pragma unroll
        for (int i = 0; i < 16; i++) {
            int col = i * 16 + q * 4;
            float4 v = *(float4*)(utmp + (size_t)r * VST + col);
            float dx = v.x - mean, dy = v.y - mean, dz = v.z - mean, dw = v.w - mean;
            s2 += dx * dx + dy * dy + dz * dz + dw * dw;
        }
        s2 += __shfl_xor_sync(0xffffffffu, s2, 1);
        s2 += __shfl_xor_sync(0xffffffffu, s2, 2);
        float rstd = rsqrtf(s2 * (1.f / 256.f) + 1e-5f);
        float* orow = out_x + (size_t)(m0 + r) * 256;
#pragma unroll
        for (int i = 0; i < 16; i++) {
            int col = i * 16 + q * 4;
            float4 v = *(float4*)(utmp + (size_t)r * VST + col);
            float4 gg = *(const float4*)(g2 + col);
            float4 bb = *(const float4*)(be2 + col);
            float4 o4;
            o4.x = (v.x - mean) * rstd * gg.x + bb.x;
            o4.y = (v.y - mean) * rstd * gg.y + bb.y;
            o4.z = (v.z - mean) * rstd * gg.z + bb.z;
            o4.w = (v.w - mean) * rstd * gg.w + bb.w;
            *(float4*)(orow + col) = o4;
        }
    }
}

// ---------------- fused CLS readout tail ----------------------------------
__device__ __forceinline__ float blk_sum256(float v, float* red, int h, int lane) {
#pragma unroll
    for (int o = 16; o; o >>= 1) v += __shfl_xor_sync(0xffffffffu, v, o);
    if (lane == 0) red[h] = v;
    __syncthreads();
    float t = 0.f;
#pragma unroll
    for (int i = 0; i < 8; i++) t += red[i];
    __syncthreads();
    return t;
}

__global__ void __launch_bounds__(256)
cls_tail(const float* __restrict__ CLS, const float* __restrict__ rkv,
         const unsigned char* __restrict__ cmask,
         const float* __restrict__ ro_w1, const float* __restrict__ ro_b1,
         const float* __restrict__ ro_w2, const float* __restrict__ ro_b2,
         const float* __restrict__ rg1, const float* __restrict__ rbe1,
         const float* __restrict__ rg2, const float* __restrict__ rbe2,
         float* __restrict__ out_c) {
    int b = blockIdx.x, tid = threadIdx.x, h = tid >> 5, lane = tid & 31;
    __shared__ float sq[256], c1s[256], h1s[256], red[8];
    __shared__ float sp[8 * 160];

    float clsv = CLS[(size_t)b * 256 + tid];
    sq[tid] = clsv;
    __syncthreads();

    const float scale = 0.17677669529663687f;
    const float* sqh = sq + h * 32;
    float svals[5];
    float smax = -INFINITY;
#pragma unroll
    for (int j = 0; j < 5; j++) {
        int m = lane + j * 32;
        float s = -INFINITY;
        if (m < NT) {
            const float* kr = rkv + (size_t)(b * NT + m) * 512 + h * 32;
            float s0 = 0.f;
#pragma unroll
            for (int d = 0; d < 32; d++) s0 = fmaf(sqh[d], kr[d], s0);
            s = s0 * scale;
            if (cmask[(size_t)b * NT + m]) s = -INFINITY;
        }
        svals[j] = s;
        smax = fmaxf(smax, s);
    }
#pragma unroll
    for (int o = 16; o; o >>= 1)
        smax = fmaxf(smax, __shfl_xor_sync(0xffffffffu, smax, o));
    float ssum = 0.f;
#pragma unroll
    for (int j = 0; j < 5; j++) {
        float p = __expf(svals[j] - smax);
        ssum += p;
        sp[h * 160 + lane + j * 32] = p;
    }
#pragma unroll
    for (int o = 16; o; o >>= 1)
        ssum += __shfl_xor_sync(0xffffffffu, ssum, o);
    __syncwarp();
    float inv = 1.f / ssum;
    float acc = 0.f;
    for (int m = 0; m < NT; m++)
        acc = fmaf(sp[h * 160 + m],
                   rkv[(size_t)(b * NT + m) * 512 + 256 + h * 32 + lane], acc);
    float v = clsv + acc * inv;
    __syncthreads();

    float mean = blk_sum256(v, red, h, lane) * (1.f / 256.f);
    float d = v - mean;
    float var = blk_sum256(d * d, red, h, lane) * (1.f / 256.f);
    float c1 = d * rsqrtf(var + 1e-5f) * rg1[tid] + rbe1[tid];
    c1s[tid] = c1;
    __syncthreads();

    {
        float a2 = 0.f;
        const float4* wr = (const float4*)(ro_w1 + (size_t)tid * 256);
#pragma unroll 8
        for (int i = 0; i < 64; i++) {
            float4 w = wr[i];
            float4 cc = *(const float4*)(c1s + i * 4);
            a2 = fmaf(w.x, cc.x, fmaf(w.y, cc.y, fmaf(w.z, cc.z, fmaf(w.w, cc.w, a2))));
        }
        h1s[tid] = fmaxf(a2 + ro_b1[tid], 0.f);
    }
    __syncthreads();

    float u;
    {
        float a2 = 0.f;
        const float4* wr = (const float4*)(ro_w2 + (size_t)tid * 256);
#pragma unroll 8
        for (int i = 0; i < 64; i++) {
            float4 w = wr[i];
            float4 cc = *(const float4*)(h1s + i * 4);
            a2 = fmaf(w.x, cc.x, fmaf(w.y, cc.y, fmaf(w.z, cc.z, fmaf(w.w, cc.w, a2))));
        }
        u = c1 + a2 + ro_b2[tid];
    }
    float mean2 = blk_sum256(u, red, h, lane) * (1.f / 256.f);
    float d2 = u - mean2;
    float var2 = blk_sum256(d2 * d2, red, h, lane) * (1.f / 256.f);
    out_c[(size_t)b * 256 + tid] = d2 * rsqrtf(var2 + 1e-5f) * rg2[tid] + rbe2[tid];
}

// ---------------- launch --------------------------------------------------
extern "C" void kernel_launch(void* const* d_in, const int* in_sizes, int n_in,
                              void* d_out, int out_size) {
    const float* node_x   = (const float*)d_in[0];
    const float* edge_x   = (const float*)d_in[1];
    const float* CLS      = (const float*)d_in[2];
    const unsigned char* nmask = (const unsigned char*)d_in[3];
    const unsigned char* cmask = (const unsigned char*)d_in[4];
    const float* w_qkv    = (const float*)d_in[5];
    const float* b_qkv    = (const float*)d_in[6];
    const float* w_kve    = (const float*)d_in[7];
    const float* b_kve    = (const float*)d_in[8];
    const float* w1       = (const float*)d_in[9];
    const float* b1       = (const float*)d_in[10];
    const float* w2       = (const float*)d_in[11];
    const float* b2       = (const float*)d_in[12];
    const float* g1       = (const float*)d_in[13];
    const float* be1      = (const float*)d_in[14];
    const float* g2       = (const float*)d_in[15];
    const float* be2      = (const float*)d_in[16];
    const float* ro_w_kv  = (const float*)d_in[17];
    const float* ro_b_kv  = (const float*)d_in[18];
    const float* ro_w1    = (const float*)d_in[19];
    const float* ro_b1    = (const float*)d_in[20];
    const float* ro_w2    = (const float*)d_in[21];
    const float* ro_b2    = (const float*)d_in[22];
    const float* ro_g1    = (const float*)d_in[23];
    const float* ro_be1   = (const float*)d_in[24];
    const float* ro_g2    = (const float*)d_in[25];
    const float* ro_be2   = (const float*)d_in[26];

    float* out_x = (float*)d_out;
    float* out_c = out_x + (size_t)BB * NN * DD;

    float *p_qkv, *p_kve, *p_attn, *p_rkv;
    __nv_bfloat16 *whi, *wlo;
    cudaGetSymbolAddress((void**)&p_qkv,  g_qkv);
    cudaGetSymbolAddress((void**)&p_kve,  g_kve);
    cudaGetSymbolAddress((void**)&p_attn, g_attn);
    cudaGetSymbolAddress((void**)&p_rkv,  g_rkv);
    cudaGetSymbolAddress((void**)&whi,    g_whi);
    cudaGetSymbolAddress((void**)&wlo,    g_wlo);

    cudaFuncSetAttribute(gemm_mma<false, false, true >, cudaFuncAttributeMaxDynamicSharedMemorySize, GEMM_SMEM);
    cudaFuncSetAttribute(gemm_mma<false, true,  false>, cudaFuncAttributeMaxDynamicSharedMemorySize, GEMM_SMEM);
    cudaFuncSetAttribute(attn_flash, cudaFuncAttributeMaxDynamicSharedMemorySize, ATT2_SMEM);
    cudaFuncSetAttribute(ffn_fused, cudaFuncAttributeMaxDynamicSharedMemorySize, FFN_SMEM);

    // fused weight conversion
    conv_all<<<(W_CONV + 255) / 256, 256>>>(w_qkv, w_kve, w1, w2, ro_w_kv, whi, wlo);

    // projections: qkv + edge-kv dual launch.
    // qkv: bx<4 (q,k cols) skip lo-pass; kve: bx<2 (k_e cols) skip.
    gemm_mma<false, false, true><<<6 * 128 + 4 * 256, 256, GEMM_SMEM>>>(
        node_x, edge_x, whi + OFF_QKV, wlo + OFF_QKV, b_qkv, p_qkv, BB * NN, 768,
        whi + OFF_KVE, wlo + OFF_KVE, b_kve, p_kve, BB * EE, 512,
        6 * 128, 6, 4, 4, 2);

    // flash attention (single-pass S)
    attn_flash<<<dim3(HH, BB), 256, ATT2_SMEM>>>(p_qkv, p_kve, nmask, p_attn);

    // fused FFN block
    ffn_fused<<<BB * NN / 64, 256, FFN_SMEM>>>(
        node_x, p_attn,
        whi + OFF_W1, wlo + OFF_W1, whi + OFF_W2, wlo + OFF_W2,
        b1, b2, g1, be1, g2, be2, out_x);

    // readout: rkv — rk cols (bx<2) skip lo-pass, rv cols keep
    gemm_mma<false, true, false><<<dim3(4, 129), 256, GEMM_SMEM>>>(
        out_x, CLS, whi + OFF_ROKV, wlo + OFF_ROKV, ro_b_kv, p_rkv, BB * NT, 512,
        nullptr, nullptr, nullptr, nullptr, 0, 0, 0, 0, 0, 2, 0);

    // fused CLS tail
    cls_tail<<<BB, 256>>>(CLS, p_rkv, cmask, ro_w1, ro_b1, ro_w2, ro_b2,
                          ro_g1, ro_be1, ro_g2, ro_be2, out_c);
}